// round 9
// baseline (speedup 1.0000x reference)
#include <cuda_runtime.h>
#include <cuda_fp16.h>
#include <math.h>

#define Bb 2
#define Ss 2048
#define Dd 1024
#define Hh 16
#define DHh 64
#define IHh 4
#define IDd 64
#define TOPK 512
#define BT (Bb*Ss)

// ---------------- scratch (device globals; no allocation allowed) ----------
__device__ float g_qkv[BT * 3 * Dd];      // 50.3 MB  [b,s, 3D] (Q|K|V) fp32
__device__ __half g_kv[BT * 2 * Dd];      // 16.8 MB  [b,s, K(1024)|V(1024)] fp16
__device__ float g_iq[BT * IHh * IDd];
__device__ float g_ik[BT * IDd];
__device__ float g_iw[BT * IHh];
__device__ int   g_sel[BT * TOPK];
__device__ int   g_cnt[BT];
__device__ float g_attn[BT * Dd];

// ---------------- tf32 helpers ----------------------------------------------
__device__ __forceinline__ unsigned t32h(float f) {
    unsigned u = __float_as_uint(f);
    return (u + 0x1000u) & 0xFFFFE000u;
}
__device__ __forceinline__ unsigned t32l(float f, unsigned h) {
    float r = f - __uint_as_float(h);
    unsigned u = __float_as_uint(r);
    return (u + 0x1000u) & 0xFFFFE000u;
}

#define MMA_TF32(ac, A0,A1,A2,A3, B0,B1)                                       \
    asm volatile("mma.sync.aligned.m16n8k8.row.col.f32.tf32.tf32.f32 "         \
                 "{%0,%1,%2,%3}, {%4,%5,%6,%7}, {%8,%9}, {%0,%1,%2,%3};"       \
                 : "+f"(ac[0]), "+f"(ac[1]), "+f"(ac[2]), "+f"(ac[3])          \
                 : "r"(A0), "r"(A1), "r"(A2), "r"(A3), "r"(B0), "r"(B1))

#define CP16(smem_u32, gptr)                                                   \
    asm volatile("cp.async.cg.shared.global [%0], [%1], 16;"                   \
                 :: "r"(smem_u32), "l"(gptr))

// ---------------- TF32 tensor-core GEMM, convert-once-to-smem --------------
// 128x128 tile, 256 threads, warp tile 64x32, mma m16n8k8.
// Raw fp32 staged via cp.async (double buffered); one conversion pass per
// K-tile writes tf32 hi/lo planes to smem; MMA phase reads operands directly
// (LDS->MMA, no inline ALU). PRECISE=true -> 3xTF32 (~fp32 accuracy).
// Dynamic smem layout (floats):
//   rawA[2][2560] @0, rawB[2][2176] @5120,
//   Ahi @9472, Alo @12032, Bhi @14592, Blo @16768; total 18944 fl = 75776 B.
#define GEMM_SMEM_BYTES (18944 * 4)

template<bool PRECISE>
__global__ __launch_bounds__(256, 2) void gemm_tc(const float* __restrict__ A,
                                                  const float* __restrict__ B,
                                                  float* __restrict__ C,
                                                  int M, int N, int K) {
    extern __shared__ float sm[];
    float* rawA = sm;              // [2][128*20]
    float* rawB = sm + 5120;       // [2][16*136]
    float* Ahi  = sm + 9472;
    float* Alo  = sm + 12032;
    float* Bhi  = sm + 14592;
    float* Blo  = sm + 16768;

    int tid = threadIdx.x;
    int lane = tid & 31, warp = tid >> 5;
    int g = lane >> 2, tg = lane & 3;
    int wm0 = (warp & 1) * 64, wn0 = (warp >> 1) * 32;
    int m0 = blockIdx.y * 128, n0 = blockIdx.x * 128;

    unsigned sRawA = (unsigned)__cvta_generic_to_shared(rawA);
    unsigned sRawB = (unsigned)__cvta_generic_to_shared(rawB);

    float acc[4][4][4];
    #pragma unroll
    for (int mi = 0; mi < 4; mi++)
        #pragma unroll
        for (int nj = 0; nj < 4; nj++)
            #pragma unroll
            for (int q = 0; q < 4; q++) acc[mi][nj][q] = 0.f;

    const int nK = K / 16;

    #define LOAD_STAGE(st, k0)                                                 \
        do {                                                                   \
            _Pragma("unroll")                                                  \
            for (int it = 0; it < 2; it++) {                                   \
                int i = tid + it * 256;                                        \
                int r = i >> 2, kk = (i & 3) * 4;                              \
                CP16(sRawA + ((st) * 2560 + r * 20 + kk) * 4,                  \
                     A + (size_t)(m0 + r) * K + (k0) + kk);                    \
                int bk = i >> 5, n4 = (i & 31) * 4;                            \
                CP16(sRawB + ((st) * 2176 + bk * 136 + n4) * 4,                \
                     B + (size_t)((k0) + bk) * N + n0 + n4);                   \
            }                                                                  \
        } while (0)

    LOAD_STAGE(0, 0);
    asm volatile("cp.async.commit_group;");

    for (int ks = 0; ks < nK; ks++) {
        int cur = ks & 1;
        if (ks + 1 < nK) {
            LOAD_STAGE(cur ^ 1, (ks + 1) * 16);
            asm volatile("cp.async.commit_group;");
            asm volatile("cp.async.wait_group 1;");
        } else {
            asm volatile("cp.async.wait_group 0;");
        }
        __syncthreads();   // raw[cur] landed; previous MMA phase done (conv planes free)

        // ---- conversion pass: each element split to tf32 hi/lo exactly once
        #pragma unroll
        for (int it = 0; it < 2; it++) {
            int i = tid + it * 256;
            {
                int off = (i >> 2) * 20 + (i & 3) * 4;
                float4 v = *(float4*)&rawA[cur * 2560 + off];
                uint4 h = make_uint4(t32h(v.x), t32h(v.y), t32h(v.z), t32h(v.w));
                *(uint4*)&Ahi[off] = h;
                if (PRECISE) {
                    uint4 l = make_uint4(t32l(v.x, h.x), t32l(v.y, h.y),
                                         t32l(v.z, h.z), t32l(v.w, h.w));
                    *(uint4*)&Alo[off] = l;
                }
            }
            {
                int off = (i >> 5) * 136 + (i & 31) * 4;
                float4 v = *(float4*)&rawB[cur * 2176 + off];
                uint4 h = make_uint4(t32h(v.x), t32h(v.y), t32h(v.z), t32h(v.w));
                *(uint4*)&Bhi[off] = h;
                if (PRECISE) {
                    uint4 l = make_uint4(t32l(v.x, h.x), t32l(v.y, h.y),
                                         t32l(v.z, h.z), t32l(v.w, h.w));
                    *(uint4*)&Blo[off] = l;
                }
            }
        }
        __syncthreads();   // converted planes ready

        // ---- MMA phase: pure LDS -> MMA
        const unsigned* ahp = (const unsigned*)Ahi;
        const unsigned* alp = (const unsigned*)Alo;
        const unsigned* bhp = (const unsigned*)Bhi;
        const unsigned* blp = (const unsigned*)Blo;
        #pragma unroll
        for (int kc = 0; kc < 16; kc += 8) {
            unsigned ah[4][4], al[4][4];
            unsigned bh[4][2], bl[4][2];
            #pragma unroll
            for (int mi = 0; mi < 4; mi++) {
                int r = wm0 + mi * 16 + g;
                ah[mi][0] = ahp[r * 20 + kc + tg];
                ah[mi][1] = ahp[(r + 8) * 20 + kc + tg];
                ah[mi][2] = ahp[r * 20 + kc + tg + 4];
                ah[mi][3] = ahp[(r + 8) * 20 + kc + tg + 4];
                if (PRECISE) {
                    al[mi][0] = alp[r * 20 + kc + tg];
                    al[mi][1] = alp[(r + 8) * 20 + kc + tg];
                    al[mi][2] = alp[r * 20 + kc + tg + 4];
                    al[mi][3] = alp[(r + 8) * 20 + kc + tg + 4];
                }
            }
            #pragma unroll
            for (int nj = 0; nj < 4; nj++) {
                int c = wn0 + nj * 8 + g;
                bh[nj][0] = bhp[(kc + tg) * 136 + c];
                bh[nj][1] = bhp[(kc + tg + 4) * 136 + c];
                if (PRECISE) {
                    bl[nj][0] = blp[(kc + tg) * 136 + c];
                    bl[nj][1] = blp[(kc + tg + 4) * 136 + c];
                }
            }
            #pragma unroll
            for (int mi = 0; mi < 4; mi++)
                #pragma unroll
                for (int nj = 0; nj < 4; nj++) {
                    MMA_TF32(acc[mi][nj], ah[mi][0], ah[mi][1], ah[mi][2], ah[mi][3],
                             bh[nj][0], bh[nj][1]);
                    if (PRECISE) {
                        MMA_TF32(acc[mi][nj], ah[mi][0], ah[mi][1], ah[mi][2], ah[mi][3],
                                 bl[nj][0], bl[nj][1]);
                        MMA_TF32(acc[mi][nj], al[mi][0], al[mi][1], al[mi][2], al[mi][3],
                                 bh[nj][0], bh[nj][1]);
                    }
                }
        }
    }
    #undef LOAD_STAGE

    #pragma unroll
    for (int mi = 0; mi < 4; mi++) {
        int r = m0 + wm0 + mi * 16 + g;
        #pragma unroll
        for (int nj = 0; nj < 4; nj++) {
            int c = n0 + wn0 + nj * 8 + tg * 2;
            *(float2*)&C[(size_t)r * N + c] = make_float2(acc[mi][nj][0], acc[mi][nj][1]);
            *(float2*)&C[(size_t)(r + 8) * N + c] = make_float2(acc[mi][nj][2], acc[mi][nj][3]);
        }
    }
}

// ---------------- scalar fp32 SGEMM (exact) for ik / iw --------------------
__global__ __launch_bounds__(256) void sgemm(const float* __restrict__ A,
                                             const float* __restrict__ B,
                                             float* __restrict__ C,
                                             int M, int N, int K) {
    __shared__ float As[64][17];
    __shared__ float Bs[16][64];
    int tid = threadIdx.x;
    int tx = tid & 15, ty = tid >> 4;
    int row0 = blockIdx.y * 64, col0 = blockIdx.x * 64;
    float acc[4][4] = {};
    for (int k0 = 0; k0 < K; k0 += 16) {
        #pragma unroll
        for (int i = 0; i < 4; i++) {
            int idx = tid + i * 256;
            int r = idx >> 4, kk = idx & 15;
            As[r][kk] = A[(size_t)(row0 + r) * K + k0 + kk];
        }
        #pragma unroll
        for (int i = 0; i < 4; i++) {
            int idx = tid + i * 256;
            int kk = idx >> 6, c = idx & 63;
            int col = col0 + c;
            Bs[kk][c] = (col < N) ? B[(size_t)(k0 + kk) * N + col] : 0.f;
        }
        __syncthreads();
        #pragma unroll
        for (int kk = 0; kk < 16; kk++) {
            float a[4], b[4];
            #pragma unroll
            for (int i = 0; i < 4; i++) a[i] = As[ty * 4 + i][kk];
            #pragma unroll
            for (int j = 0; j < 4; j++) b[j] = Bs[kk][tx * 4 + j];
            #pragma unroll
            for (int i = 0; i < 4; i++)
                #pragma unroll
                for (int j = 0; j < 4; j++)
                    acc[i][j] += a[i] * b[j];
        }
        __syncthreads();
    }
    #pragma unroll
    for (int i = 0; i < 4; i++) {
        int r = row0 + ty * 4 + i;
        #pragma unroll
        for (int j = 0; j < 4; j++) {
            int c = col0 + tx * 4 + j;
            if (c < N) C[(size_t)r * N + c] = acc[i][j];
        }
    }
}

// ---------------- RoPE: Q in-place fp32; K -> fp16 kv buffer ---------------
__global__ __launch_bounds__(256) void rope_kernel(float* __restrict__ qkv,
                                                   __half* __restrict__ kv) {
    int idx = blockIdx.x * blockDim.x + threadIdx.x;
    const int per = Bb * Ss * Hh * (DHh / 2);
    if (idx >= 2 * per) return;
    int which = (idx >= per) ? 1 : 0;
    int r = idx - which * per;
    int p = r & 31;  r >>= 5;
    int h = r & 15;  r >>= 4;
    int s = r & 2047; r >>= 11;
    int b = r;
    double theta = pow(10000.0, -(2.0 * p) / 64.0);
    float ang = (float)((double)s * theta);
    float sn, cn;
    sincosf(ang, &sn, &cn);
    int bt = b * Ss + s;
    size_t base = (size_t)bt * (3 * Dd) + which * Dd + h * 64 + 2 * p;
    float x0 = qkv[base], x1 = qkv[base + 1];
    float y0 = x0 * cn - x1 * sn;
    float y1 = x1 * cn + x0 * sn;
    if (which == 0) {
        qkv[base]     = y0;      // Q stays fp32 (read by sdpa)
        qkv[base + 1] = y1;
    } else {
        *(__half2*)(kv + (size_t)bt * 2048 + h * 64 + 2 * p) = __floats2half2_rn(y0, y1);
    }
}

// ---------------- convert V to fp16 (K handled by rope) --------------------
__global__ __launch_bounds__(256) void cvt_v(const float* __restrict__ qkv,
                                             __half* __restrict__ kv) {
    int idx = blockIdx.x * 256 + threadIdx.x;
    int e = idx * 4;
    int bt = e >> 10;
    int off = e & 1023;
    float4 v = *(const float4*)&qkv[(size_t)bt * 3072 + 2048 + off];
    __half2 p0 = __floats2half2_rn(v.x, v.y);
    __half2 p1 = __floats2half2_rn(v.z, v.w);
    uint2 o;
    o.x = *reinterpret_cast<unsigned*>(&p0);
    o.y = *reinterpret_cast<unsigned*>(&p1);
    *(uint2*)(kv + (size_t)bt * 2048 + 1024 + off) = o;
}

__device__ __forceinline__ unsigned flipf(float f) {
    unsigned u = __float_as_uint(f);
    return (u & 0x80000000u) ? ~u : (u | 0x80000000u);
}

// ---------------- indexer scores + exact causal top-k ----------------------
__global__ __launch_bounds__(256) void indexer_topk(const float* __restrict__ iq,
                                                    const float* __restrict__ ik,
                                                    const float* __restrict__ iw,
                                                    int* __restrict__ sel,
                                                    int* __restrict__ cnt) {
    int bt = blockIdx.x;
    int b = bt >> 11, t = bt & 2047;
    int tid = threadIdx.x;
    int lane = tid & 31, w = tid >> 5;
    int n = t + 1;

    __shared__ float sq[IHh * IDd];
    __shared__ float sw[IHh];
    if (tid < IHh * IDd) sq[tid] = iq[(size_t)bt * IHh * IDd + tid];
    if (tid < IHh) sw[tid] = iw[bt * IHh + tid];

    if (n <= TOPK) {
        for (int s = tid; s < n; s += 256) sel[(size_t)bt * TOPK + s] = s;
        if (tid == 0) cnt[bt] = n;
        return;
    }
    __syncthreads();

    __shared__ float sc[Ss];
    for (int s = tid; s < n; s += 256) {
        const float4* k4 = (const float4*)(ik + (size_t)(b * Ss + s) * IDd);
        float d0 = 0.f, d1 = 0.f, d2 = 0.f, d3 = 0.f;
        #pragma unroll
        for (int j4 = 0; j4 < 16; j4++) {
            float4 kv = k4[j4];
            int o = j4 * 4;
            d0 += sq[0*64+o]*kv.x + sq[0*64+o+1]*kv.y + sq[0*64+o+2]*kv.z + sq[0*64+o+3]*kv.w;
            d1 += sq[1*64+o]*kv.x + sq[1*64+o+1]*kv.y + sq[1*64+o+2]*kv.z + sq[1*64+o+3]*kv.w;
            d2 += sq[2*64+o]*kv.x + sq[2*64+o+1]*kv.y + sq[2*64+o+2]*kv.z + sq[2*64+o+3]*kv.w;
            d3 += sq[3*64+o]*kv.x + sq[3*64+o+1]*kv.y + sq[3*64+o+2]*kv.z + sq[3*64+o+3]*kv.w;
        }
        sc[s] = sw[0]*fmaxf(d0,0.f) + sw[1]*fmaxf(d1,0.f)
              + sw[2]*fmaxf(d2,0.f) + sw[3]*fmaxf(d3,0.f);
    }
    __syncthreads();

    // MSB radix select with warp-aggregated histogram + parallel suffix scan
    __shared__ int hist[256];
    __shared__ int sfx[256];
    __shared__ unsigned sh_prefix;
    __shared__ int sh_krem;
    unsigned prefix = 0;
    int krem = TOPK;
    for (int pass = 0; pass < 4; pass++) {
        int shift = 24 - pass * 8;
        hist[tid] = 0;
        __syncthreads();
        for (int s0 = 0; s0 < n; s0 += 256) {
            int s = s0 + tid;
            bool valid = false;
            unsigned bin = 0;
            if (s < n) {
                unsigned key = flipf(sc[s]);
                if (((key >> shift) >> 8) == prefix) {
                    valid = true;
                    bin = (key >> shift) & 255;
                }
            }
            unsigned act = __ballot_sync(0xffffffffu, valid);
            if (valid) {
                unsigned peers = __match_any_sync(act, bin);
                if ((__ffs(peers) - 1) == lane)
                    atomicAdd(&hist[bin], __popc(peers));
            }
        }
        __syncthreads();
        int hv = hist[tid];
        sfx[tid] = hv;
        __syncthreads();
        #pragma unroll
        for (int off = 1; off < 256; off <<= 1) {
            int add = (tid + off < 256) ? sfx[tid + off] : 0;
            __syncthreads();
            sfx[tid] += add;
            __syncthreads();
        }
        int sf = sfx[tid];
        int sfn = (tid < 255) ? sfx[tid + 1] : 0;
        if (sf >= krem && sfn < krem) {
            sh_prefix = (prefix << 8) | (unsigned)tid;
            sh_krem = krem - sfn;
        }
        __syncthreads();
        prefix = sh_prefix;
        krem = sh_krem;
        __syncthreads();
    }
    unsigned T = prefix;

    __shared__ int nsel;
    if (tid == 0) nsel = 0;
    __syncthreads();
    for (int s = tid; s < n; s += 256) {
        if (flipf(sc[s]) > T) {
            int p = atomicAdd(&nsel, 1);
            sel[(size_t)bt * TOPK + p] = s;
        }
    }
    __syncthreads();

    // equals: take the krem SMALLEST indices (matches jax top_k tie-break)
    __shared__ int warpcnt[8];
    __shared__ int eqbase;
    if (tid == 0) eqbase = 0;
    __syncthreads();
    for (int s0 = 0; s0 < n; s0 += 256) {
        int s = s0 + tid;
        bool eq = false;
        if (s < n) eq = (flipf(sc[s]) == T);
        unsigned bal = __ballot_sync(0xffffffffu, eq);
        if (lane == 0) warpcnt[w] = __popc(bal);
        __syncthreads();
        int wbase = 0;
        for (int i = 0; i < w; i++) wbase += warpcnt[i];
        int rank = eqbase + wbase + __popc(bal & ((1u << lane) - 1));
        if (eq && rank < krem) {
            int p = atomicAdd(&nsel, 1);
            sel[(size_t)bt * TOPK + p] = s;
        }
        __syncthreads();
        if (tid == 0) {
            int tot = 0;
            for (int i = 0; i < 8; i++) tot += warpcnt[i];
            eqbase += tot;
        }
        __syncthreads();
    }
    if (tid == 0) cnt[bt] = TOPK;
}

// ---------------- sparse SDPA: block per (b,t, head-half), warp per head ---
__global__ __launch_bounds__(256, 2) void sdpa(const float* __restrict__ qkv,
                                               const __half* __restrict__ kv,
                                               const int* __restrict__ sel,
                                               const int* __restrict__ cnt,
                                               float* __restrict__ attn) {
    int bt = blockIdx.x;
    int b = bt >> 11;
    int tid = threadIdx.x;
    int w = tid >> 5, lane = tid & 31;
    int h = blockIdx.y * 8 + w;

    __shared__ float sQ[8 * DHh];
    __shared__ int   sSel[TOPK];
    __shared__ float sL[8][TOPK];

    int n = cnt[bt];
    const float* Qrow = qkv + (size_t)bt * 3 * Dd + blockIdx.y * 512;
    for (int i = tid; i < 512; i += 256) sQ[i] = Qrow[i];
    for (int i = tid; i < n; i += 256) sSel[i] = sel[(size_t)bt * TOPK + i];
    __syncthreads();

    float qr[64];
    #pragma unroll
    for (int i = 0; i < 64; i += 4) {
        float4 tq = *(const float4*)&sQ[w * 64 + i];
        qr[i] = tq.x; qr[i+1] = tq.y; qr[i+2] = tq.z; qr[i+3] = tq.w;
    }

    const float scale = 0.125f;
    size_t kvbase = (size_t)b * Ss * 2048;

    // Phase A: logits (lane-per-key, fp16 K, 512B per warp instruction)
    for (int j0 = 0; j0 < n; j0 += 32) {
        int j = j0 + lane;
        if (j < n) {
            int s = sSel[j];
            const uint4* kp = (const uint4*)(kv + kvbase + (size_t)s * 2048 + h * 64);
            float d = 0.f;
            #pragma unroll
            for (int i = 0; i < 8; i++) {
                uint4 wv = kp[i];
                const __half2* p2 = (const __half2*)&wv;
                #pragma unroll
                for (int q = 0; q < 4; q++) {
                    float2 f = __half22float2(p2[q]);
                    d += qr[i*8 + q*2] * f.x + qr[i*8 + q*2 + 1] * f.y;
                }
            }
            sL[w][j] = d * scale;
        }
    }
    __syncwarp();

    // Phase B: softmax (warp-local per head)
    float m = -1e30f;
    for (int j = lane; j < n; j += 32) m = fmaxf(m, sL[w][j]);
    #pragma unroll
    for (int o = 16; o; o >>= 1) m = fmaxf(m, __shfl_xor_sync(0xffffffffu, m, o));
    float sum = 0.f;
    for (int j = lane; j < n; j += 32) {
        float p = __expf(sL[w][j] - m);
        sL[w][j] = p;
        sum += p;
    }
    #pragma unroll
    for (int o = 16; o; o >>= 1) sum += __shfl_xor_sync(0xffffffffu, sum, o);
    float inv = 1.f / sum;
    __syncwarp();

    // Phase C: P @ V, vectorized 4 keys/instruction.
    int kg = lane >> 3, dg = lane & 7;
    float acc[8] = {};
    #pragma unroll 4
    for (int j0 = 0; j0 < n; j0 += 4) {
        int j = j0 + kg;
        if (j < n) {
            float p = sL[w][j];
            int s = sSel[j];
            uint4 vv = *(const uint4*)(kv + kvbase + (size_t)s * 2048 + 1024 + h * 64 + dg * 8);
            const __half2* h2 = (const __half2*)&vv;
            #pragma unroll
            for (int q = 0; q < 4; q++) {
                float2 f = __half22float2(h2[q]);
                acc[2*q]     += p * f.x;
                acc[2*q + 1] += p * f.y;
            }
        }
    }
    #pragma unroll
    for (int q = 0; q < 8; q++) {
        acc[q] += __shfl_xor_sync(0xffffffffu, acc[q], 8);
        acc[q] += __shfl_xor_sync(0xffffffffu, acc[q], 16);
    }
    if (kg == 0) {
        size_t ob = (size_t)bt * Dd + h * 64 + dg * 8;
        float4 o0 = make_float4(acc[0] * inv, acc[1] * inv, acc[2] * inv, acc[3] * inv);
        float4 o1 = make_float4(acc[4] * inv, acc[5] * inv, acc[6] * inv, acc[7] * inv);
        *(float4*)&attn[ob]     = o0;
        *(float4*)&attn[ob + 4] = o1;
    }
}

// ---------------- launch ----------------------------------------------------
extern "C" void kernel_launch(void* const* d_in, const int* in_sizes, int n_in,
                              void* d_out, int out_size) {
    const float* x      = (const float*)d_in[0];
    const float* W_qkv  = (const float*)d_in[1];
    const float* W_o    = (const float*)d_in[2];
    const float* Wq_idx = (const float*)d_in[3];
    const float* Wk_idx = (const float*)d_in[4];
    const float* Ww_idx = (const float*)d_in[5];
    float* out = (float*)d_out;

    float *qkv, *iq, *ik, *iw, *attn;
    __half* kv;
    int *sel, *cnt;
    cudaGetSymbolAddress((void**)&qkv,  g_qkv);
    cudaGetSymbolAddress((void**)&kv,   g_kv);
    cudaGetSymbolAddress((void**)&iq,   g_iq);
    cudaGetSymbolAddress((void**)&ik,   g_ik);
    cudaGetSymbolAddress((void**)&iw,   g_iw);
    cudaGetSymbolAddress((void**)&attn, g_attn);
    cudaGetSymbolAddress((void**)&sel,  g_sel);
    cudaGetSymbolAddress((void**)&cnt,  g_cnt);

    // opt in to 74KB dynamic smem (idempotent; immediate API, capture-safe)
    cudaFuncSetAttribute(gemm_tc<true>, cudaFuncAttributeMaxDynamicSharedMemorySize,
                         GEMM_SMEM_BYTES);

    const int M = BT;  // 4096

    // QKV projection (3xTF32 compensated, convert-once-to-smem)
    gemm_tc<true><<<dim3(3 * Dd / 128, M / 128), 256, GEMM_SMEM_BYTES>>>(
        x, W_qkv, qkv, M, 3 * Dd, Dd);
    // RoPE: Q fp32 in-place, K straight into fp16 kv buffer
    rope_kernel<<<(2 * Bb * Ss * Hh * 32 + 255) / 256, 256>>>(qkv, kv);
    // V -> fp16 kv buffer
    cvt_v<<<(BT * Dd / 4) / 256, 256>>>(qkv, kv);
    // indexer projections: iq via 3xTF32 (near-exact), ik/iw scalar exact
    gemm_tc<true><<<dim3(IHh * IDd / 128, M / 128), 256, GEMM_SMEM_BYTES>>>(
        x, Wq_idx, iq, M, IHh * IDd, Dd);
    sgemm<<<dim3(1, M / 64), 256>>>(x, Wk_idx, ik, M, IDd, Dd);
    sgemm<<<dim3(1, M / 64), 256>>>(x, Ww_idx, iw, M, IHh, Dd);
    // indexer scores + top-k selection
    indexer_topk<<<BT, 256>>>(iq, ik, iw, sel, cnt);
    // sparse attention (2 head-halves per (b,t))
    sdpa<<<dim3(BT, 2), 256>>>(qkv, kv, sel, cnt, attn);
    // output projection (3xTF32 compensated)
    gemm_tc<true><<<dim3(Dd / 128, M / 128), 256, GEMM_SMEM_BYTES>>>(
        attn, W_o, out, M, Dd, Dd);
}

// round 12
// speedup vs baseline: 1.0524x; 1.0524x over previous
#include <cuda_runtime.h>
#include <cuda_fp16.h>
#include <math.h>

#define Bb 2
#define Ss 2048
#define Dd 1024
#define Hh 16
#define DHh 64
#define IHh 4
#define IDd 64
#define TOPK 512
#define BT (Bb*Ss)
#define NKW 68   // packed Wk(64)|Ww(4)

// ---------------- scratch (device globals; no allocation allowed) ----------
__device__ float g_qkv[BT * 3 * Dd];      // 50.3 MB  [b,s, 3D] (Q|K|V) fp32
__device__ __half g_kv[BT * 2 * Dd];      // 16.8 MB  [b,s, K(1024)|V(1024)] fp16
__device__ float g_iq[BT * IHh * IDd];    // iq projections (3xTF32, as R8)
__device__ float g_wkw[Dd * NKW];         // packed Wk|Ww
__device__ float g_ikw[BT * NKW];         // fused ik|iw projections (exact fp32)
__device__ int   g_sel[BT * TOPK];
__device__ int   g_cnt[BT];
__device__ float g_attn[BT * Dd];

// ---------------- tf32 helpers (cvt.rna == (u+0x1000)&~0x1FFF, bit-identical)
__device__ __forceinline__ unsigned t32h(float f) {
    unsigned u;
    asm("cvt.rna.tf32.f32 %0, %1;" : "=r"(u) : "f"(f));
    return u;
}
__device__ __forceinline__ unsigned t32l(float f, unsigned h) {
    float r = f - __uint_as_float(h);
    unsigned u;
    asm("cvt.rna.tf32.f32 %0, %1;" : "=r"(u) : "f"(r));
    return u;
}

#define MMA_TF32(ac, A0,A1,A2,A3, B0,B1)                                       \
    asm volatile("mma.sync.aligned.m16n8k8.row.col.f32.tf32.tf32.f32 "         \
                 "{%0,%1,%2,%3}, {%4,%5,%6,%7}, {%8,%9}, {%0,%1,%2,%3};"       \
                 : "+f"(ac[0]), "+f"(ac[1]), "+f"(ac[2]), "+f"(ac[3])          \
                 : "r"(A0), "r"(A1), "r"(A2), "r"(A3), "r"(B0), "r"(B1))

#define CP16(smem_u32, gptr)                                                   \
    asm volatile("cp.async.cg.shared.global [%0], [%1], 16;"                   \
                 :: "r"(smem_u32), "l"(gptr))

// ---------------- TF32 tensor-core GEMM, cp.async double-buffered ----------
// (R8 structure — inline convert, now via cvt.rna; proven best.)
// 128x128 tile, 256 threads, warp tile 64x32, mma m16n8k8.
// PRECISE=true -> 3xTF32 (hi/lo split, ~fp32 accuracy).
template<bool PRECISE>
__global__ __launch_bounds__(256, 2) void gemm_tc(const float* __restrict__ A,
                                                  const float* __restrict__ B,
                                                  float* __restrict__ C,
                                                  int M, int N, int K) {
    __shared__ __align__(16) float As[2][128 * 20];
    __shared__ __align__(16) float Bs[2][16 * 136];
    int tid = threadIdx.x;
    int lane = tid & 31, warp = tid >> 5;
    int g = lane >> 2, tg = lane & 3;
    int wm0 = (warp & 1) * 64, wn0 = (warp >> 1) * 32;
    int m0 = blockIdx.y * 128, n0 = blockIdx.x * 128;

    unsigned sA0 = (unsigned)__cvta_generic_to_shared(&As[0][0]);
    unsigned sB0 = (unsigned)__cvta_generic_to_shared(&Bs[0][0]);

    float acc[4][4][4];
    #pragma unroll
    for (int mi = 0; mi < 4; mi++)
        #pragma unroll
        for (int nj = 0; nj < 4; nj++)
            #pragma unroll
            for (int q = 0; q < 4; q++) acc[mi][nj][q] = 0.f;

    const int nK = K / 16;

    #define LOAD_STAGE(st, k0)                                                 \
        do {                                                                   \
            _Pragma("unroll")                                                  \
            for (int it = 0; it < 2; it++) {                                   \
                int i = tid + it * 256;                                        \
                int r = i >> 2, kk = (i & 3) * 4;                              \
                CP16(sA0 + ((st) * 2560 + r * 20 + kk) * 4,                    \
                     A + (size_t)(m0 + r) * K + (k0) + kk);                    \
                int bk = i >> 5, n4 = (i & 31) * 4;                            \
                CP16(sB0 + ((st) * 2176 + bk * 136 + n4) * 4,                  \
                     B + (size_t)((k0) + bk) * N + n0 + n4);                   \
            }                                                                  \
        } while (0)

    LOAD_STAGE(0, 0);
    asm volatile("cp.async.commit_group;");

    for (int ks = 0; ks < nK; ks++) {
        int cur = ks & 1;
        if (ks + 1 < nK) {
            LOAD_STAGE(cur ^ 1, (ks + 1) * 16);
            asm volatile("cp.async.commit_group;");
            asm volatile("cp.async.wait_group 1;");
        } else {
            asm volatile("cp.async.wait_group 0;");
        }
        __syncthreads();

        const float* as = As[cur];
        const float* bs = Bs[cur];
        #pragma unroll
        for (int kc = 0; kc < 16; kc += 8) {
            unsigned ah[4][4], al[4][4];
            unsigned bh[4][2], bl[4][2];
            #pragma unroll
            for (int mi = 0; mi < 4; mi++) {
                int r = wm0 + mi * 16 + g;
                float v0 = as[r * 20 + kc + tg];
                float v1 = as[(r + 8) * 20 + kc + tg];
                float v2 = as[r * 20 + kc + tg + 4];
                float v3 = as[(r + 8) * 20 + kc + tg + 4];
                ah[mi][0] = t32h(v0); ah[mi][1] = t32h(v1);
                ah[mi][2] = t32h(v2); ah[mi][3] = t32h(v3);
                if (PRECISE) {
                    al[mi][0] = t32l(v0, ah[mi][0]); al[mi][1] = t32l(v1, ah[mi][1]);
                    al[mi][2] = t32l(v2, ah[mi][2]); al[mi][3] = t32l(v3, ah[mi][3]);
                }
            }
            #pragma unroll
            for (int nj = 0; nj < 4; nj++) {
                int c = wn0 + nj * 8 + g;
                float v0 = bs[(kc + tg) * 136 + c];
                float v1 = bs[(kc + tg + 4) * 136 + c];
                bh[nj][0] = t32h(v0); bh[nj][1] = t32h(v1);
                if (PRECISE) {
                    bl[nj][0] = t32l(v0, bh[nj][0]);
                    bl[nj][1] = t32l(v1, bh[nj][1]);
                }
            }
            #pragma unroll
            for (int mi = 0; mi < 4; mi++)
                #pragma unroll
                for (int nj = 0; nj < 4; nj++) {
                    MMA_TF32(acc[mi][nj], ah[mi][0], ah[mi][1], ah[mi][2], ah[mi][3],
                             bh[nj][0], bh[nj][1]);
                    if (PRECISE) {
                        MMA_TF32(acc[mi][nj], ah[mi][0], ah[mi][1], ah[mi][2], ah[mi][3],
                                 bl[nj][0], bl[nj][1]);
                        MMA_TF32(acc[mi][nj], al[mi][0], al[mi][1], al[mi][2], al[mi][3],
                                 bh[nj][0], bh[nj][1]);
                    }
                }
        }
        __syncthreads();
    }
    #undef LOAD_STAGE

    #pragma unroll
    for (int mi = 0; mi < 4; mi++) {
        int r = m0 + wm0 + mi * 16 + g;
        #pragma unroll
        for (int nj = 0; nj < 4; nj++) {
            int c = n0 + wn0 + nj * 8 + tg * 2;
            *(float2*)&C[(size_t)r * N + c] = make_float2(acc[mi][nj][0], acc[mi][nj][1]);
            *(float2*)&C[(size_t)(r + 8) * N + c] = make_float2(acc[mi][nj][2], acc[mi][nj][3]);
        }
    }
}

// ---------------- scalar fp32 SGEMM (exact) for fused ik|iw ----------------
__global__ __launch_bounds__(256) void sgemm(const float* __restrict__ A,
                                             const float* __restrict__ B,
                                             float* __restrict__ C,
                                             int M, int N, int K) {
    __shared__ float As[64][17];
    __shared__ float Bs[16][64];
    int tid = threadIdx.x;
    int tx = tid & 15, ty = tid >> 4;
    int row0 = blockIdx.y * 64, col0 = blockIdx.x * 64;
    float acc[4][4] = {};
    for (int k0 = 0; k0 < K; k0 += 16) {
        #pragma unroll
        for (int i = 0; i < 4; i++) {
            int idx = tid + i * 256;
            int r = idx >> 4, kk = idx & 15;
            As[r][kk] = A[(size_t)(row0 + r) * K + k0 + kk];
        }
        #pragma unroll
        for (int i = 0; i < 4; i++) {
            int idx = tid + i * 256;
            int kk = idx >> 6, c = idx & 63;
            int col = col0 + c;
            Bs[kk][c] = (col < N) ? B[(size_t)(k0 + kk) * N + col] : 0.f;
        }
        __syncthreads();
        #pragma unroll
        for (int kk = 0; kk < 16; kk++) {
            float a[4], b[4];
            #pragma unroll
            for (int i = 0; i < 4; i++) a[i] = As[ty * 4 + i][kk];
            #pragma unroll
            for (int j = 0; j < 4; j++) b[j] = Bs[kk][tx * 4 + j];
            #pragma unroll
            for (int i = 0; i < 4; i++)
                #pragma unroll
                for (int j = 0; j < 4; j++)
                    acc[i][j] += a[i] * b[j];
        }
        __syncthreads();
    }
    #pragma unroll
    for (int i = 0; i < 4; i++) {
        int r = row0 + ty * 4 + i;
        #pragma unroll
        for (int j = 0; j < 4; j++) {
            int c = col0 + tx * 4 + j;
            if (c < N) C[(size_t)r * N + c] = acc[i][j];
        }
    }
}

// ---------------- pack Wk|Ww -> [1024, 68] ----------------------------------
__global__ __launch_bounds__(256) void pack_wkw(const float* __restrict__ Wk,
                                                const float* __restrict__ Ww,
                                                float* __restrict__ Wkw) {
    int idx = blockIdx.x * 256 + threadIdx.x;
    if (idx >= Dd * NKW) return;
    int row = idx / NKW, col = idx - row * NKW;
    Wkw[idx] = (col < 64) ? Wk[row * 64 + col] : Ww[row * IHh + (col - 64)];
}

// ---------------- fused RoPE (Q fp32, K fp16) + V fp16 conversion ----------
__global__ __launch_bounds__(256) void rope_cvt(float* __restrict__ qkv,
                                                __half* __restrict__ kv) {
    int idx = blockIdx.x * blockDim.x + threadIdx.x;
    const int per = Bb * Ss * Hh * (DHh / 2);   // 2,097,152
    if (idx < 2 * per) {
        // RoPE on Q (which=0) / K (which=1)
        int which = (idx >= per) ? 1 : 0;
        int r = idx - which * per;
        int p = r & 31;  r >>= 5;
        int h = r & 15;  r >>= 4;
        int s = r & 2047; r >>= 11;
        int b = r;
        double theta = pow(10000.0, -(2.0 * p) / 64.0);
        float ang = (float)((double)s * theta);
        float sn, cn;
        sincosf(ang, &sn, &cn);
        int bt = b * Ss + s;
        size_t base = (size_t)bt * (3 * Dd) + which * Dd + h * 64 + 2 * p;
        float x0 = qkv[base], x1 = qkv[base + 1];
        float y0 = x0 * cn - x1 * sn;
        float y1 = x1 * cn + x0 * sn;
        if (which == 0) {
            qkv[base]     = y0;
            qkv[base + 1] = y1;
        } else {
            *(__half2*)(kv + (size_t)bt * 2048 + h * 64 + 2 * p) = __floats2half2_rn(y0, y1);
        }
    } else {
        // V -> fp16 (4 elements per thread)
        int vi = idx - 2 * per;
        if (vi >= BT * Dd / 4) return;
        int e = vi * 4;
        int bt = e >> 10;
        int off = e & 1023;
        float4 v = *(const float4*)&qkv[(size_t)bt * 3072 + 2048 + off];
        __half2 p0 = __floats2half2_rn(v.x, v.y);
        __half2 p1 = __floats2half2_rn(v.z, v.w);
        uint2 o;
        o.x = *reinterpret_cast<unsigned*>(&p0);
        o.y = *reinterpret_cast<unsigned*>(&p1);
        *(uint2*)(kv + (size_t)bt * 2048 + 1024 + off) = o;
    }
}

__device__ __forceinline__ unsigned flipf(float f) {
    unsigned u = __float_as_uint(f);
    return (u & 0x80000000u) ? ~u : (u | 0x80000000u);
}

// ---------------- indexer scores + exact causal top-k ----------------------
// iq: [BT,256] (3xTF32, as R8); ikw: [BT,68] exact fp32 (ik @0, iw @64).
__global__ __launch_bounds__(256) void indexer_topk(const float* __restrict__ iq,
                                                    const float* __restrict__ ikw,
                                                    int* __restrict__ sel,
                                                    int* __restrict__ cnt) {
    int bt = blockIdx.x;
    int b = bt >> 11, t = bt & 2047;
    int tid = threadIdx.x;
    int lane = tid & 31, w = tid >> 5;
    int n = t + 1;

    __shared__ float sq[IHh * IDd];
    __shared__ float sw[IHh];
    if (tid < IHh * IDd) sq[tid] = iq[(size_t)bt * IHh * IDd + tid];
    if (tid < IHh) sw[tid] = ikw[(size_t)bt * NKW + 64 + tid];

    if (n <= TOPK) {
        for (int s = tid; s < n; s += 256) sel[(size_t)bt * TOPK + s] = s;
        if (tid == 0) cnt[bt] = n;
        return;
    }
    __syncthreads();

    __shared__ float sc[Ss];
    for (int s = tid; s < n; s += 256) {
        const float4* k4 = (const float4*)(ikw + (size_t)(b * Ss + s) * NKW);
        float d0 = 0.f, d1 = 0.f, d2 = 0.f, d3 = 0.f;
        #pragma unroll
        for (int j4 = 0; j4 < 16; j4++) {
            float4 kv = k4[j4];
            int o = j4 * 4;
            d0 += sq[0*64+o]*kv.x + sq[0*64+o+1]*kv.y + sq[0*64+o+2]*kv.z + sq[0*64+o+3]*kv.w;
            d1 += sq[1*64+o]*kv.x + sq[1*64+o+1]*kv.y + sq[1*64+o+2]*kv.z + sq[1*64+o+3]*kv.w;
            d2 += sq[2*64+o]*kv.x + sq[2*64+o+1]*kv.y + sq[2*64+o+2]*kv.z + sq[2*64+o+3]*kv.w;
            d3 += sq[3*64+o]*kv.x + sq[3*64+o+1]*kv.y + sq[3*64+o+2]*kv.z + sq[3*64+o+3]*kv.w;
        }
        sc[s] = sw[0]*fmaxf(d0,0.f) + sw[1]*fmaxf(d1,0.f)
              + sw[2]*fmaxf(d2,0.f) + sw[3]*fmaxf(d3,0.f);
    }
    __syncthreads();

    // MSB radix select with warp-aggregated histogram + parallel suffix scan
    __shared__ int hist[256];
    __shared__ int sfx[256];
    __shared__ unsigned sh_prefix;
    __shared__ int sh_krem;
    unsigned prefix = 0;
    int krem = TOPK;
    for (int pass = 0; pass < 4; pass++) {
        int shift = 24 - pass * 8;
        hist[tid] = 0;
        __syncthreads();
        for (int s0 = 0; s0 < n; s0 += 256) {
            int s = s0 + tid;
            bool valid = false;
            unsigned bin = 0;
            if (s < n) {
                unsigned key = flipf(sc[s]);
                if (((key >> shift) >> 8) == prefix) {
                    valid = true;
                    bin = (key >> shift) & 255;
                }
            }
            unsigned act = __ballot_sync(0xffffffffu, valid);
            if (valid) {
                unsigned peers = __match_any_sync(act, bin);
                if ((__ffs(peers) - 1) == lane)
                    atomicAdd(&hist[bin], __popc(peers));
            }
        }
        __syncthreads();
        int hv = hist[tid];
        sfx[tid] = hv;
        __syncthreads();
        #pragma unroll
        for (int off = 1; off < 256; off <<= 1) {
            int add = (tid + off < 256) ? sfx[tid + off] : 0;
            __syncthreads();
            sfx[tid] += add;
            __syncthreads();
        }
        int sf = sfx[tid];
        int sfn = (tid < 255) ? sfx[tid + 1] : 0;
        if (sf >= krem && sfn < krem) {
            sh_prefix = (prefix << 8) | (unsigned)tid;
            sh_krem = krem - sfn;
        }
        __syncthreads();
        prefix = sh_prefix;
        krem = sh_krem;
        __syncthreads();
    }
    unsigned T = prefix;

    __shared__ int nsel;
    if (tid == 0) nsel = 0;
    __syncthreads();
    for (int s = tid; s < n; s += 256) {
        if (flipf(sc[s]) > T) {
            int p = atomicAdd(&nsel, 1);
            sel[(size_t)bt * TOPK + p] = s;
        }
    }
    __syncthreads();

    // equals: take the krem SMALLEST indices (matches jax top_k tie-break)
    __shared__ int warpcnt[8];
    __shared__ int eqbase;
    if (tid == 0) eqbase = 0;
    __syncthreads();
    for (int s0 = 0; s0 < n; s0 += 256) {
        int s = s0 + tid;
        bool eq = false;
        if (s < n) eq = (flipf(sc[s]) == T);
        unsigned bal = __ballot_sync(0xffffffffu, eq);
        if (lane == 0) warpcnt[w] = __popc(bal);
        __syncthreads();
        int wbase = 0;
        for (int i = 0; i < w; i++) wbase += warpcnt[i];
        int rank = eqbase + wbase + __popc(bal & ((1u << lane) - 1));
        if (eq && rank < krem) {
            int p = atomicAdd(&nsel, 1);
            sel[(size_t)bt * TOPK + p] = s;
        }
        __syncthreads();
        if (tid == 0) {
            int tot = 0;
            for (int i = 0; i < 8; i++) tot += warpcnt[i];
            eqbase += tot;
        }
        __syncthreads();
    }
    if (tid == 0) cnt[bt] = TOPK;
}

// ---------------- sparse SDPA: block per (b,t, head-half), warp per head ---
__global__ __launch_bounds__(256, 2) void sdpa(const float* __restrict__ qkv,
                                               const __half* __restrict__ kv,
                                               const int* __restrict__ sel,
                                               const int* __restrict__ cnt,
                                               float* __restrict__ attn) {
    int bt = blockIdx.x;
    int b = bt >> 11;
    int tid = threadIdx.x;
    int w = tid >> 5, lane = tid & 31;
    int h = blockIdx.y * 8 + w;

    __shared__ float sQ[8 * DHh];
    __shared__ int   sSel[TOPK];
    __shared__ float sL[8][TOPK];

    int n = cnt[bt];
    const float* Qrow = qkv + (size_t)bt * 3 * Dd + blockIdx.y * 512;
    for (int i = tid; i < 512; i += 256) sQ[i] = Qrow[i];
    for (int i = tid; i < n; i += 256) sSel[i] = sel[(size_t)bt * TOPK + i];
    __syncthreads();

    float qr[64];
    #pragma unroll
    for (int i = 0; i < 64; i += 4) {
        float4 tq = *(const float4*)&sQ[w * 64 + i];
        qr[i] = tq.x; qr[i+1] = tq.y; qr[i+2] = tq.z; qr[i+3] = tq.w;
    }

    const float scale = 0.125f;
    size_t kvbase = (size_t)b * Ss * 2048;

    // Phase A: logits (lane-per-key, fp16 K, 512B per warp instruction)
    for (int j0 = 0; j0 < n; j0 += 32) {
        int j = j0 + lane;
        if (j < n) {
            int s = sSel[j];
            const uint4* kp = (const uint4*)(kv + kvbase + (size_t)s * 2048 + h * 64);
            float d = 0.f;
            #pragma unroll
            for (int i = 0; i < 8; i++) {
                uint4 wv = kp[i];
                const __half2* p2 = (const __half2*)&wv;
                #pragma unroll
                for (int q = 0; q < 4; q++) {
                    float2 f = __half22float2(p2[q]);
                    d += qr[i*8 + q*2] * f.x + qr[i*8 + q*2 + 1] * f.y;
                }
            }
            sL[w][j] = d * scale;
        }
    }
    __syncwarp();

    // Phase B: softmax (warp-local per head)
    float m = -1e30f;
    for (int j = lane; j < n; j += 32) m = fmaxf(m, sL[w][j]);
    #pragma unroll
    for (int o = 16; o; o >>= 1) m = fmaxf(m, __shfl_xor_sync(0xffffffffu, m, o));
    float sum = 0.f;
    for (int j = lane; j < n; j += 32) {
        float p = __expf(sL[w][j] - m);
        sL[w][j] = p;
        sum += p;
    }
    #pragma unroll
    for (int o = 16; o; o >>= 1) sum += __shfl_xor_sync(0xffffffffu, sum, o);
    float inv = 1.f / sum;
    __syncwarp();

    // Phase C: P @ V, vectorized 4 keys/instruction.
    int kg = lane >> 3, dg = lane & 7;
    float acc[8] = {};
    #pragma unroll 4
    for (int j0 = 0; j0 < n; j0 += 4) {
        int j = j0 + kg;
        if (j < n) {
            float p = sL[w][j];
            int s = sSel[j];
            uint4 vv = *(const uint4*)(kv + kvbase + (size_t)s * 2048 + 1024 + h * 64 + dg * 8);
            const __half2* h2 = (const __half2*)&vv;
            #pragma unroll
            for (int q = 0; q < 4; q++) {
                float2 f = __half22float2(h2[q]);
                acc[2*q]     += p * f.x;
                acc[2*q + 1] += p * f.y;
            }
        }
    }
    #pragma unroll
    for (int q = 0; q < 8; q++) {
        acc[q] += __shfl_xor_sync(0xffffffffu, acc[q], 8);
        acc[q] += __shfl_xor_sync(0xffffffffu, acc[q], 16);
    }
    if (kg == 0) {
        size_t ob = (size_t)bt * Dd + h * 64 + dg * 8;
        float4 o0 = make_float4(acc[0] * inv, acc[1] * inv, acc[2] * inv, acc[3] * inv);
        float4 o1 = make_float4(acc[4] * inv, acc[5] * inv, acc[6] * inv, acc[7] * inv);
        *(float4*)&attn[ob]     = o0;
        *(float4*)&attn[ob + 4] = o1;
    }
}

// ---------------- launch ----------------------------------------------------
extern "C" void kernel_launch(void* const* d_in, const int* in_sizes, int n_in,
                              void* d_out, int out_size) {
    const float* x      = (const float*)d_in[0];
    const float* W_qkv  = (const float*)d_in[1];
    const float* W_o    = (const float*)d_in[2];
    const float* Wq_idx = (const float*)d_in[3];
    const float* Wk_idx = (const float*)d_in[4];
    const float* Ww_idx = (const float*)d_in[5];
    float* out = (float*)d_out;

    float *qkv, *iq, *wkw, *ikw, *attn;
    __half* kv;
    int *sel, *cnt;
    cudaGetSymbolAddress((void**)&qkv,  g_qkv);
    cudaGetSymbolAddress((void**)&kv,   g_kv);
    cudaGetSymbolAddress((void**)&iq,   g_iq);
    cudaGetSymbolAddress((void**)&wkw,  g_wkw);
    cudaGetSymbolAddress((void**)&ikw,  g_ikw);
    cudaGetSymbolAddress((void**)&attn, g_attn);
    cudaGetSymbolAddress((void**)&sel,  g_sel);
    cudaGetSymbolAddress((void**)&cnt,  g_cnt);

    const int M = BT;  // 4096

    // QKV projection (3xTF32 compensated)
    gemm_tc<true><<<dim3(3 * Dd / 128, M / 128), 256>>>(x, W_qkv, qkv, M, 3 * Dd, Dd);
    // RoPE (Q fp32 in-place, K -> fp16) + V -> fp16, one launch
    {
        int total = 2 * Bb * Ss * Hh * 32 + BT * Dd / 4;
        rope_cvt<<<(total + 255) / 256, 256>>>(qkv, kv);
    }
    // iq projection (3xTF32, as R8)
    gemm_tc<true><<<dim3(IHh * IDd / 128, M / 128), 256>>>(x, Wq_idx, iq, M, IHh * IDd, Dd);
    // ik|iw fused projection: exact fp32, bit-identical per column to R8
    pack_wkw<<<(Dd * NKW + 255) / 256, 256>>>(Wk_idx, Ww_idx, wkw);
    sgemm<<<dim3(2, M / 64), 256>>>(x, wkw, ikw, M, NKW, Dd);
    // indexer scores + top-k selection
    indexer_topk<<<BT, 256>>>(iq, ikw, sel, cnt);
    // sparse attention (2 head-halves per (b,t))
    sdpa<<<dim3(BT, 2), 256>>>(qkv, kv, sel, cnt, attn);
    // output projection (3xTF32 compensated)
    gemm_tc<true><<<dim3(Dd / 128, M / 128), 256>>>(attn, W_o, out, M, Dd, Dd);
}

// round 13
// speedup vs baseline: 1.3690x; 1.3009x over previous
#include <cuda_runtime.h>
#include <cuda_fp16.h>
#include <math.h>

#define Bb 2
#define Ss 2048
#define Dd 1024
#define Hh 16
#define DHh 64
#define IHh 4
#define IDd 64
#define TOPK 512
#define BT (Bb*Ss)
#define NKW 68   // packed Wk(64)|Ww(4)

// ---------------- scratch (device globals; no allocation allowed) ----------
__device__ float g_qkv[BT * 3 * Dd];      // only Q region written now (fp32)
__device__ __half g_kv[BT * 2 * Dd];      // [b,s, K(1024)|V(1024)] fp16
__device__ float2 g_tab[Ss * 32];         // RoPE (cos,sin) per (s, p)
__device__ float g_iq[BT * IHh * IDd];    // iq projections (3xTF32)
__device__ float g_wkw[Dd * NKW];         // packed Wk|Ww
__device__ float g_ikw[BT * NKW];         // fused ik|iw projections (exact fp32)
__device__ int   g_sel[BT * TOPK];
__device__ int   g_cnt[BT];
__device__ float g_attn[BT * Dd];

// ---------------- tf32 helpers ----------------------------------------------
__device__ __forceinline__ unsigned t32h(float f) {
    unsigned u;
    asm("cvt.rna.tf32.f32 %0, %1;" : "=r"(u) : "f"(f));
    return u;
}
__device__ __forceinline__ unsigned t32l(float f, unsigned h) {
    float r = f - __uint_as_float(h);
    unsigned u;
    asm("cvt.rna.tf32.f32 %0, %1;" : "=r"(u) : "f"(r));
    return u;
}

#define MMA_TF32(ac, A0,A1,A2,A3, B0,B1)                                       \
    asm volatile("mma.sync.aligned.m16n8k8.row.col.f32.tf32.tf32.f32 "         \
                 "{%0,%1,%2,%3}, {%4,%5,%6,%7}, {%8,%9}, {%0,%1,%2,%3};"       \
                 : "+f"(ac[0]), "+f"(ac[1]), "+f"(ac[2]), "+f"(ac[3])          \
                 : "r"(A0), "r"(A1), "r"(A2), "r"(A3), "r"(B0), "r"(B1))

#define CP16(smem_u32, gptr)                                                   \
    asm volatile("cp.async.cg.shared.global [%0], [%1], 16;"                   \
                 :: "r"(smem_u32), "l"(gptr))

// ---------------- RoPE cos/sin table (identical math to prior rope kernel) --
__global__ __launch_bounds__(256) void rope_table(float2* __restrict__ tab) {
    int idx = blockIdx.x * 256 + threadIdx.x;
    if (idx >= Ss * 32) return;
    int s = idx >> 5, p = idx & 31;
    double theta = pow(10000.0, -(2.0 * p) / 64.0);
    float ang = (float)((double)s * theta);
    float sn, cn;
    sincosf(ang, &sn, &cn);
    tab[idx] = make_float2(cn, sn);
}

// ---------------- TF32 tensor-core GEMM, cp.async double-buffered ----------
// 128x128 tile, 256 threads, warp tile 64x32, mma m16n8k8.
// PRECISE=true -> 3xTF32 (hi/lo split, ~fp32 accuracy).
// EPI=1 -> fused QKV epilogue: Q rotate->fp32 C; K rotate->fp16 kv; V ->fp16 kv.
//          (bit-identical to the old store->reload->rope/convert path)
template<bool PRECISE, int EPI>
__global__ __launch_bounds__(256, 2) void gemm_tc(const float* __restrict__ A,
                                                  const float* __restrict__ B,
                                                  float* __restrict__ C,
                                                  int M, int N, int K,
                                                  const float2* __restrict__ tab,
                                                  __half* __restrict__ kvp) {
    __shared__ __align__(16) float As[2][128 * 20];
    __shared__ __align__(16) float Bs[2][16 * 136];
    int tid = threadIdx.x;
    int lane = tid & 31, warp = tid >> 5;
    int g = lane >> 2, tg = lane & 3;
    int wm0 = (warp & 1) * 64, wn0 = (warp >> 1) * 32;
    int m0 = blockIdx.y * 128, n0 = blockIdx.x * 128;

    unsigned sA0 = (unsigned)__cvta_generic_to_shared(&As[0][0]);
    unsigned sB0 = (unsigned)__cvta_generic_to_shared(&Bs[0][0]);

    float acc[4][4][4];
    #pragma unroll
    for (int mi = 0; mi < 4; mi++)
        #pragma unroll
        for (int nj = 0; nj < 4; nj++)
            #pragma unroll
            for (int q = 0; q < 4; q++) acc[mi][nj][q] = 0.f;

    const int nK = K / 16;

    #define LOAD_STAGE(st, k0)                                                 \
        do {                                                                   \
            _Pragma("unroll")                                                  \
            for (int it = 0; it < 2; it++) {                                   \
                int i = tid + it * 256;                                        \
                int r = i >> 2, kk = (i & 3) * 4;                              \
                CP16(sA0 + ((st) * 2560 + r * 20 + kk) * 4,                    \
                     A + (size_t)(m0 + r) * K + (k0) + kk);                    \
                int bk = i >> 5, n4 = (i & 31) * 4;                            \
                CP16(sB0 + ((st) * 2176 + bk * 136 + n4) * 4,                  \
                     B + (size_t)((k0) + bk) * N + n0 + n4);                   \
            }                                                                  \
        } while (0)

    LOAD_STAGE(0, 0);
    asm volatile("cp.async.commit_group;");

    for (int ks = 0; ks < nK; ks++) {
        int cur = ks & 1;
        if (ks + 1 < nK) {
            LOAD_STAGE(cur ^ 1, (ks + 1) * 16);
            asm volatile("cp.async.commit_group;");
            asm volatile("cp.async.wait_group 1;");
        } else {
            asm volatile("cp.async.wait_group 0;");
        }
        __syncthreads();

        const float* as = As[cur];
        const float* bs = Bs[cur];
        #pragma unroll
        for (int kc = 0; kc < 16; kc += 8) {
            unsigned ah[4][4], al[4][4];
            unsigned bh[4][2], bl[4][2];
            #pragma unroll
            for (int mi = 0; mi < 4; mi++) {
                int r = wm0 + mi * 16 + g;
                float v0 = as[r * 20 + kc + tg];
                float v1 = as[(r + 8) * 20 + kc + tg];
                float v2 = as[r * 20 + kc + tg + 4];
                float v3 = as[(r + 8) * 20 + kc + tg + 4];
                ah[mi][0] = t32h(v0); ah[mi][1] = t32h(v1);
                ah[mi][2] = t32h(v2); ah[mi][3] = t32h(v3);
                if (PRECISE) {
                    al[mi][0] = t32l(v0, ah[mi][0]); al[mi][1] = t32l(v1, ah[mi][1]);
                    al[mi][2] = t32l(v2, ah[mi][2]); al[mi][3] = t32l(v3, ah[mi][3]);
                }
            }
            #pragma unroll
            for (int nj = 0; nj < 4; nj++) {
                int c = wn0 + nj * 8 + g;
                float v0 = bs[(kc + tg) * 136 + c];
                float v1 = bs[(kc + tg + 4) * 136 + c];
                bh[nj][0] = t32h(v0); bh[nj][1] = t32h(v1);
                if (PRECISE) {
                    bl[nj][0] = t32l(v0, bh[nj][0]);
                    bl[nj][1] = t32l(v1, bh[nj][1]);
                }
            }
            #pragma unroll
            for (int mi = 0; mi < 4; mi++)
                #pragma unroll
                for (int nj = 0; nj < 4; nj++) {
                    MMA_TF32(acc[mi][nj], ah[mi][0], ah[mi][1], ah[mi][2], ah[mi][3],
                             bh[nj][0], bh[nj][1]);
                    if (PRECISE) {
                        MMA_TF32(acc[mi][nj], ah[mi][0], ah[mi][1], ah[mi][2], ah[mi][3],
                                 bl[nj][0], bl[nj][1]);
                        MMA_TF32(acc[mi][nj], al[mi][0], al[mi][1], al[mi][2], al[mi][3],
                                 bh[nj][0], bh[nj][1]);
                    }
                }
        }
        __syncthreads();
    }
    #undef LOAD_STAGE

    if (EPI == 0) {
        #pragma unroll
        for (int mi = 0; mi < 4; mi++) {
            int r = m0 + wm0 + mi * 16 + g;
            #pragma unroll
            for (int nj = 0; nj < 4; nj++) {
                int c = n0 + wn0 + nj * 8 + tg * 2;
                *(float2*)&C[(size_t)r * N + c] = make_float2(acc[mi][nj][0], acc[mi][nj][1]);
                *(float2*)&C[(size_t)(r + 8) * N + c] = make_float2(acc[mi][nj][2], acc[mi][nj][3]);
            }
        }
    } else {
        // Fused QKV epilogue. Whole 128-col block is inside one region.
        int region = n0 >> 10;   // 0=Q, 1=K, 2=V
        #pragma unroll
        for (int mi = 0; mi < 4; mi++) {
            int r = m0 + wm0 + mi * 16 + g;       // global token index (bt)
            int s = r & 2047;                     // seq position (r+8 stays in-batch)
            #pragma unroll
            for (int nj = 0; nj < 4; nj++) {
                int c = n0 + wn0 + nj * 8 + tg * 2;   // even column
                int cc = c & 1023;                    // offset within region
                float a0 = acc[mi][nj][0], a1 = acc[mi][nj][1];
                float a2 = acc[mi][nj][2], a3 = acc[mi][nj][3];
                if (region == 2) {
                    *(__half2*)(kvp + (size_t)r * 2048 + 1024 + cc) = __floats2half2_rn(a0, a1);
                    *(__half2*)(kvp + (size_t)(r + 8) * 2048 + 1024 + cc) = __floats2half2_rn(a2, a3);
                } else {
                    int p = (cc & 63) >> 1;
                    float2 t0 = tab[s * 32 + p];
                    float2 t1 = tab[(s + 8) * 32 + p];
                    float y0 = a0 * t0.x - a1 * t0.y;
                    float y1 = a1 * t0.x + a0 * t0.y;
                    float y2 = a2 * t1.x - a3 * t1.y;
                    float y3 = a3 * t1.x + a2 * t1.y;
                    if (region == 0) {
                        *(float2*)&C[(size_t)r * N + c] = make_float2(y0, y1);
                        *(float2*)&C[(size_t)(r + 8) * N + c] = make_float2(y2, y3);
                    } else {
                        *(__half2*)(kvp + (size_t)r * 2048 + cc) = __floats2half2_rn(y0, y1);
                        *(__half2*)(kvp + (size_t)(r + 8) * 2048 + cc) = __floats2half2_rn(y2, y3);
                    }
                }
            }
        }
    }
}

// ---------------- scalar fp32 SGEMM (exact) for fused ik|iw ----------------
__global__ __launch_bounds__(256) void sgemm(const float* __restrict__ A,
                                             const float* __restrict__ B,
                                             float* __restrict__ C,
                                             int M, int N, int K) {
    __shared__ float As[64][17];
    __shared__ float Bs[16][64];
    int tid = threadIdx.x;
    int tx = tid & 15, ty = tid >> 4;
    int row0 = blockIdx.y * 64, col0 = blockIdx.x * 64;
    float acc[4][4] = {};
    for (int k0 = 0; k0 < K; k0 += 16) {
        #pragma unroll
        for (int i = 0; i < 4; i++) {
            int idx = tid + i * 256;
            int r = idx >> 4, kk = idx & 15;
            As[r][kk] = A[(size_t)(row0 + r) * K + k0 + kk];
        }
        #pragma unroll
        for (int i = 0; i < 4; i++) {
            int idx = tid + i * 256;
            int kk = idx >> 6, c = idx & 63;
            int col = col0 + c;
            Bs[kk][c] = (col < N) ? B[(size_t)(k0 + kk) * N + col] : 0.f;
        }
        __syncthreads();
        #pragma unroll
        for (int kk = 0; kk < 16; kk++) {
            float a[4], b[4];
            #pragma unroll
            for (int i = 0; i < 4; i++) a[i] = As[ty * 4 + i][kk];
            #pragma unroll
            for (int j = 0; j < 4; j++) b[j] = Bs[kk][tx * 4 + j];
            #pragma unroll
            for (int i = 0; i < 4; i++)
                #pragma unroll
                for (int j = 0; j < 4; j++)
                    acc[i][j] += a[i] * b[j];
        }
        __syncthreads();
    }
    #pragma unroll
    for (int i = 0; i < 4; i++) {
        int r = row0 + ty * 4 + i;
        #pragma unroll
        for (int j = 0; j < 4; j++) {
            int c = col0 + tx * 4 + j;
            if (c < N) C[(size_t)r * N + c] = acc[i][j];
        }
    }
}

// ---------------- pack Wk|Ww -> [1024, 68] ----------------------------------
__global__ __launch_bounds__(256) void pack_wkw(const float* __restrict__ Wk,
                                                const float* __restrict__ Ww,
                                                float* __restrict__ Wkw) {
    int idx = blockIdx.x * 256 + threadIdx.x;
    if (idx >= Dd * NKW) return;
    int row = idx / NKW, col = idx - row * NKW;
    Wkw[idx] = (col < 64) ? Wk[row * 64 + col] : Ww[row * IHh + (col - 64)];
}

__device__ __forceinline__ unsigned flipf(float f) {
    unsigned u = __float_as_uint(f);
    return (u & 0x80000000u) ? ~u : (u | 0x80000000u);
}

// ---------------- indexer scores + exact causal top-k ----------------------
__global__ __launch_bounds__(256) void indexer_topk(const float* __restrict__ iq,
                                                    const float* __restrict__ ikw,
                                                    int* __restrict__ sel,
                                                    int* __restrict__ cnt) {
    int bt = blockIdx.x;
    int b = bt >> 11, t = bt & 2047;
    int tid = threadIdx.x;
    int lane = tid & 31, w = tid >> 5;
    int n = t + 1;

    __shared__ float sq[IHh * IDd];
    __shared__ float sw[IHh];
    if (tid < IHh * IDd) sq[tid] = iq[(size_t)bt * IHh * IDd + tid];
    if (tid < IHh) sw[tid] = ikw[(size_t)bt * NKW + 64 + tid];

    if (n <= TOPK) {
        for (int s = tid; s < n; s += 256) sel[(size_t)bt * TOPK + s] = s;
        if (tid == 0) cnt[bt] = n;
        return;
    }
    __syncthreads();

    __shared__ float sc[Ss];
    for (int s = tid; s < n; s += 256) {
        const float4* k4 = (const float4*)(ikw + (size_t)(b * Ss + s) * NKW);
        float d0 = 0.f, d1 = 0.f, d2 = 0.f, d3 = 0.f;
        #pragma unroll
        for (int j4 = 0; j4 < 16; j4++) {
            float4 kv = k4[j4];
            int o = j4 * 4;
            d0 += sq[0*64+o]*kv.x + sq[0*64+o+1]*kv.y + sq[0*64+o+2]*kv.z + sq[0*64+o+3]*kv.w;
            d1 += sq[1*64+o]*kv.x + sq[1*64+o+1]*kv.y + sq[1*64+o+2]*kv.z + sq[1*64+o+3]*kv.w;
            d2 += sq[2*64+o]*kv.x + sq[2*64+o+1]*kv.y + sq[2*64+o+2]*kv.z + sq[2*64+o+3]*kv.w;
            d3 += sq[3*64+o]*kv.x + sq[3*64+o+1]*kv.y + sq[3*64+o+2]*kv.z + sq[3*64+o+3]*kv.w;
        }
        sc[s] = sw[0]*fmaxf(d0,0.f) + sw[1]*fmaxf(d1,0.f)
              + sw[2]*fmaxf(d2,0.f) + sw[3]*fmaxf(d3,0.f);
    }
    __syncthreads();

    __shared__ int hist[256];
    __shared__ int sfx[256];
    __shared__ unsigned sh_prefix;
    __shared__ int sh_krem;
    unsigned prefix = 0;
    int krem = TOPK;
    for (int pass = 0; pass < 4; pass++) {
        int shift = 24 - pass * 8;
        hist[tid] = 0;
        __syncthreads();
        for (int s0 = 0; s0 < n; s0 += 256) {
            int s = s0 + tid;
            bool valid = false;
            unsigned bin = 0;
            if (s < n) {
                unsigned key = flipf(sc[s]);
                if (((key >> shift) >> 8) == prefix) {
                    valid = true;
                    bin = (key >> shift) & 255;
                }
            }
            unsigned act = __ballot_sync(0xffffffffu, valid);
            if (valid) {
                unsigned peers = __match_any_sync(act, bin);
                if ((__ffs(peers) - 1) == lane)
                    atomicAdd(&hist[bin], __popc(peers));
            }
        }
        __syncthreads();
        int hv = hist[tid];
        sfx[tid] = hv;
        __syncthreads();
        #pragma unroll
        for (int off = 1; off < 256; off <<= 1) {
            int add = (tid + off < 256) ? sfx[tid + off] : 0;
            __syncthreads();
            sfx[tid] += add;
            __syncthreads();
        }
        int sf = sfx[tid];
        int sfn = (tid < 255) ? sfx[tid + 1] : 0;
        if (sf >= krem && sfn < krem) {
            sh_prefix = (prefix << 8) | (unsigned)tid;
            sh_krem = krem - sfn;
        }
        __syncthreads();
        prefix = sh_prefix;
        krem = sh_krem;
        __syncthreads();
    }
    unsigned T = prefix;

    __shared__ int nsel;
    if (tid == 0) nsel = 0;
    __syncthreads();
    for (int s = tid; s < n; s += 256) {
        if (flipf(sc[s]) > T) {
            int p = atomicAdd(&nsel, 1);
            sel[(size_t)bt * TOPK + p] = s;
        }
    }
    __syncthreads();

    __shared__ int warpcnt[8];
    __shared__ int eqbase;
    if (tid == 0) eqbase = 0;
    __syncthreads();
    for (int s0 = 0; s0 < n; s0 += 256) {
        int s = s0 + tid;
        bool eq = false;
        if (s < n) eq = (flipf(sc[s]) == T);
        unsigned bal = __ballot_sync(0xffffffffu, eq);
        if (lane == 0) warpcnt[w] = __popc(bal);
        __syncthreads();
        int wbase = 0;
        for (int i = 0; i < w; i++) wbase += warpcnt[i];
        int rank = eqbase + wbase + __popc(bal & ((1u << lane) - 1));
        if (eq && rank < krem) {
            int p = atomicAdd(&nsel, 1);
            sel[(size_t)bt * TOPK + p] = s;
        }
        __syncthreads();
        if (tid == 0) {
            int tot = 0;
            for (int i = 0; i < 8; i++) tot += warpcnt[i];
            eqbase += tot;
        }
        __syncthreads();
    }
    if (tid == 0) cnt[bt] = TOPK;
}

// ---------------- sparse SDPA: block per (b,t, head-half), warp per head ---
__global__ __launch_bounds__(256, 2) void sdpa(const float* __restrict__ qkv,
                                               const __half* __restrict__ kv,
                                               const int* __restrict__ sel,
                                               const int* __restrict__ cnt,
                                               float* __restrict__ attn) {
    int bt = blockIdx.x;
    int b = bt >> 11;
    int tid = threadIdx.x;
    int w = tid >> 5, lane = tid & 31;
    int h = blockIdx.y * 8 + w;

    __shared__ float sQ[8 * DHh];
    __shared__ int   sSel[TOPK];
    __shared__ float sL[8][TOPK];

    int n = cnt[bt];
    const float* Qrow = qkv + (size_t)bt * 3 * Dd + blockIdx.y * 512;
    for (int i = tid; i < 512; i += 256) sQ[i] = Qrow[i];
    for (int i = tid; i < n; i += 256) sSel[i] = sel[(size_t)bt * TOPK + i];
    __syncthreads();

    float qr[64];
    #pragma unroll
    for (int i = 0; i < 64; i += 4) {
        float4 tq = *(const float4*)&sQ[w * 64 + i];
        qr[i] = tq.x; qr[i+1] = tq.y; qr[i+2] = tq.z; qr[i+3] = tq.w;
    }

    const float scale = 0.125f;
    size_t kvbase = (size_t)b * Ss * 2048;

    // Phase A: logits (lane-per-key, fp16 K)
    for (int j0 = 0; j0 < n; j0 += 32) {
        int j = j0 + lane;
        if (j < n) {
            int s = sSel[j];
            const uint4* kp = (const uint4*)(kv + kvbase + (size_t)s * 2048 + h * 64);
            float d = 0.f;
            #pragma unroll
            for (int i = 0; i < 8; i++) {
                uint4 wv = kp[i];
                const __half2* p2 = (const __half2*)&wv;
                #pragma unroll
                for (int q = 0; q < 4; q++) {
                    float2 f = __half22float2(p2[q]);
                    d += qr[i*8 + q*2] * f.x + qr[i*8 + q*2 + 1] * f.y;
                }
            }
            sL[w][j] = d * scale;
        }
    }
    __syncwarp();

    // Phase B: softmax (warp-local per head)
    float m = -1e30f;
    for (int j = lane; j < n; j += 32) m = fmaxf(m, sL[w][j]);
    #pragma unroll
    for (int o = 16; o; o >>= 1) m = fmaxf(m, __shfl_xor_sync(0xffffffffu, m, o));
    float sum = 0.f;
    for (int j = lane; j < n; j += 32) {
        float p = __expf(sL[w][j] - m);
        sL[w][j] = p;
        sum += p;
    }
    #pragma unroll
    for (int o = 16; o; o >>= 1) sum += __shfl_xor_sync(0xffffffffu, sum, o);
    float inv = 1.f / sum;
    __syncwarp();

    // Phase C: P @ V, vectorized 4 keys/instruction.
    int kg = lane >> 3, dg = lane & 7;
    float acc[8] = {};
    #pragma unroll 4
    for (int j0 = 0; j0 < n; j0 += 4) {
        int j = j0 + kg;
        if (j < n) {
            float p = sL[w][j];
            int s = sSel[j];
            uint4 vv = *(const uint4*)(kv + kvbase + (size_t)s * 2048 + 1024 + h * 64 + dg * 8);
            const __half2* h2 = (const __half2*)&vv;
            #pragma unroll
            for (int q = 0; q < 4; q++) {
                float2 f = __half22float2(h2[q]);
                acc[2*q]     += p * f.x;
                acc[2*q + 1] += p * f.y;
            }
        }
    }
    #pragma unroll
    for (int q = 0; q < 8; q++) {
        acc[q] += __shfl_xor_sync(0xffffffffu, acc[q], 8);
        acc[q] += __shfl_xor_sync(0xffffffffu, acc[q], 16);
    }
    if (kg == 0) {
        size_t ob = (size_t)bt * Dd + h * 64 + dg * 8;
        float4 o0 = make_float4(acc[0] * inv, acc[1] * inv, acc[2] * inv, acc[3] * inv);
        float4 o1 = make_float4(acc[4] * inv, acc[5] * inv, acc[6] * inv, acc[7] * inv);
        *(float4*)&attn[ob]     = o0;
        *(float4*)&attn[ob + 4] = o1;
    }
}

// ---------------- launch ----------------------------------------------------
extern "C" void kernel_launch(void* const* d_in, const int* in_sizes, int n_in,
                              void* d_out, int out_size) {
    const float* x      = (const float*)d_in[0];
    const float* W_qkv  = (const float*)d_in[1];
    const float* W_o    = (const float*)d_in[2];
    const float* Wq_idx = (const float*)d_in[3];
    const float* Wk_idx = (const float*)d_in[4];
    const float* Ww_idx = (const float*)d_in[5];
    float* out = (float*)d_out;

    float *qkv, *iq, *wkw, *ikw, *attn;
    float2* tab;
    __half* kv;
    int *sel, *cnt;
    cudaGetSymbolAddress((void**)&qkv,  g_qkv);
    cudaGetSymbolAddress((void**)&kv,   g_kv);
    cudaGetSymbolAddress((void**)&tab,  g_tab);
    cudaGetSymbolAddress((void**)&iq,   g_iq);
    cudaGetSymbolAddress((void**)&wkw,  g_wkw);
    cudaGetSymbolAddress((void**)&ikw,  g_ikw);
    cudaGetSymbolAddress((void**)&attn, g_attn);
    cudaGetSymbolAddress((void**)&sel,  g_sel);
    cudaGetSymbolAddress((void**)&cnt,  g_cnt);

    const int M = BT;  // 4096

    // RoPE table (identical math to previous per-thread computation)
    rope_table<<<(Ss * 32 + 255) / 256, 256>>>(tab);
    // QKV projection with fused RoPE + fp16 K/V epilogue (bit-identical)
    gemm_tc<true, 1><<<dim3(3 * Dd / 128, M / 128), 256>>>(
        x, W_qkv, qkv, M, 3 * Dd, Dd, tab, kv);
    // iq projection (3xTF32)
    gemm_tc<true, 0><<<dim3(IHh * IDd / 128, M / 128), 256>>>(
        x, Wq_idx, iq, M, IHh * IDd, Dd, nullptr, nullptr);
    // ik|iw fused projection: exact fp32
    pack_wkw<<<(Dd * NKW + 255) / 256, 256>>>(Wk_idx, Ww_idx, wkw);
    sgemm<<<dim3(2, M / 64), 256>>>(x, wkw, ikw, M, NKW, Dd);
    // indexer scores + top-k selection
    indexer_topk<<<BT, 256>>>(iq, ikw, sel, cnt);
    // sparse attention (2 head-halves per (b,t))
    sdpa<<<dim3(BT, 2), 256>>>(qkv, kv, sel, cnt, attn);
    // output projection (3xTF32)
    gemm_tc<true, 0><<<dim3(Dd / 128, M / 128), 256>>>(
        attn, W_o, out, M, Dd, Dd, nullptr, nullptr);
}

// round 14
// speedup vs baseline: 1.4223x; 1.0389x over previous
#include <cuda_runtime.h>
#include <cuda_fp16.h>
#include <math.h>

#define Bb 2
#define Ss 2048
#define Dd 1024
#define Hh 16
#define DHh 64
#define IHh 4
#define IDd 64
#define TOPK 512
#define BT (Bb*Ss)
#define NKW 68    // packed Wk(64)|Ww(4)
#define NFUSE 3328  // 3072 (QKV) + 256 (iq)

// ---------------- scratch (device globals; no allocation allowed) ----------
__device__ float g_q[BT * Dd];            // post-RoPE Q (fp32)
__device__ __half g_kv[BT * 2 * Dd];      // [b,s, K(1024)|V(1024)] fp16
__device__ float2 g_tab[Ss * 32];         // RoPE (cos,sin) per (s, p)
__device__ float g_iq[BT * IHh * IDd];    // iq projections (3xTF32)
__device__ float g_wkw[Dd * NKW];         // packed Wk|Ww
__device__ float g_ikw[BT * NKW];         // fused ik|iw projections (exact fp32)
__device__ int   g_sel[BT * TOPK];
__device__ int   g_cnt[BT];
__device__ float g_attn[BT * Dd];

// ---------------- tf32 helpers ----------------------------------------------
__device__ __forceinline__ unsigned t32h(float f) {
    unsigned u;
    asm("cvt.rna.tf32.f32 %0, %1;" : "=r"(u) : "f"(f));
    return u;
}
__device__ __forceinline__ unsigned t32l(float f, unsigned h) {
    float r = f - __uint_as_float(h);
    unsigned u;
    asm("cvt.rna.tf32.f32 %0, %1;" : "=r"(u) : "f"(r));
    return u;
}

#define MMA_TF32(ac, A0,A1,A2,A3, B0,B1)                                       \
    asm volatile("mma.sync.aligned.m16n8k8.row.col.f32.tf32.tf32.f32 "         \
                 "{%0,%1,%2,%3}, {%4,%5,%6,%7}, {%8,%9}, {%0,%1,%2,%3};"       \
                 : "+f"(ac[0]), "+f"(ac[1]), "+f"(ac[2]), "+f"(ac[3])          \
                 : "r"(A0), "r"(A1), "r"(A2), "r"(A3), "r"(B0), "r"(B1))

#define CP16(smem_u32, gptr)                                                   \
    asm volatile("cp.async.cg.shared.global [%0], [%1], 16;"                   \
                 :: "r"(smem_u32), "l"(gptr))

// ---------------- RoPE cos/sin table ----------------------------------------
__global__ __launch_bounds__(256) void rope_table(float2* __restrict__ tab) {
    int idx = blockIdx.x * 256 + threadIdx.x;
    if (idx >= Ss * 32) return;
    int s = idx >> 5, p = idx & 31;
    double theta = pow(10000.0, -(2.0 * p) / 64.0);
    float ang = (float)((double)s * theta);
    float sn, cn;
    sincosf(ang, &sn, &cn);
    tab[idx] = make_float2(cn, sn);
}

// ---------------- TF32 tensor-core GEMM, cp.async double-buffered ----------
// 128x128 tile, 256 threads, warp tile 64x32, mma m16n8k8.
// PRECISE=true -> 3xTF32 (hi/lo split, ~fp32 accuracy).
// EPI=1 -> fused launch over N=3328: per-block B source is W_qkv (n0<3072,
//          stride 3072) or B2=Wq_idx (stride 256). Epilogue by region:
//          0: Q rotate->fp32 qp (stride 1024); 1: K rotate->fp16 kv;
//          2: V ->fp16 kv; 3: iq ->fp32 C2 (stride 256).
//          All data paths bit-identical to the separate-launch versions.
template<bool PRECISE, int EPI>
__global__ __launch_bounds__(256, 2) void gemm_tc(const float* __restrict__ A,
                                                  const float* __restrict__ B,
                                                  float* __restrict__ C,
                                                  int M, int N, int K,
                                                  const float2* __restrict__ tab,
                                                  __half* __restrict__ kvp,
                                                  const float* __restrict__ B2,
                                                  float* __restrict__ C2) {
    __shared__ __align__(16) float As[2][128 * 20];
    __shared__ __align__(16) float Bs[2][16 * 136];
    int tid = threadIdx.x;
    int lane = tid & 31, warp = tid >> 5;
    int g = lane >> 2, tg = lane & 3;
    int wm0 = (warp & 1) * 64, wn0 = (warp >> 1) * 32;
    int m0 = blockIdx.y * 128, n0 = blockIdx.x * 128;

    // per-block B source (uniform)
    const float* Bp = B;
    int Nb = (EPI == 1) ? 3072 : N;
    int nb0 = n0;
    if (EPI == 1 && n0 >= 3072) { Bp = B2; Nb = 256; nb0 = n0 - 3072; }

    unsigned sA0 = (unsigned)__cvta_generic_to_shared(&As[0][0]);
    unsigned sB0 = (unsigned)__cvta_generic_to_shared(&Bs[0][0]);

    float acc[4][4][4];
    #pragma unroll
    for (int mi = 0; mi < 4; mi++)
        #pragma unroll
        for (int nj = 0; nj < 4; nj++)
            #pragma unroll
            for (int q = 0; q < 4; q++) acc[mi][nj][q] = 0.f;

    const int nK = K / 16;

    #define LOAD_STAGE(st, k0)                                                 \
        do {                                                                   \
            _Pragma("unroll")                                                  \
            for (int it = 0; it < 2; it++) {                                   \
                int i = tid + it * 256;                                        \
                int r = i >> 2, kk = (i & 3) * 4;                              \
                CP16(sA0 + ((st) * 2560 + r * 20 + kk) * 4,                    \
                     A + (size_t)(m0 + r) * K + (k0) + kk);                    \
                int bk = i >> 5, n4 = (i & 31) * 4;                            \
                CP16(sB0 + ((st) * 2176 + bk * 136 + n4) * 4,                  \
                     Bp + (size_t)((k0) + bk) * Nb + nb0 + n4);                \
            }                                                                  \
        } while (0)

    LOAD_STAGE(0, 0);
    asm volatile("cp.async.commit_group;");

    for (int ks = 0; ks < nK; ks++) {
        int cur = ks & 1;
        if (ks + 1 < nK) {
            LOAD_STAGE(cur ^ 1, (ks + 1) * 16);
            asm volatile("cp.async.commit_group;");
            asm volatile("cp.async.wait_group 1;");
        } else {
            asm volatile("cp.async.wait_group 0;");
        }
        __syncthreads();

        const float* as = As[cur];
        const float* bs = Bs[cur];
        #pragma unroll
        for (int kc = 0; kc < 16; kc += 8) {
            unsigned ah[4][4], al[4][4];
            unsigned bh[4][2], bl[4][2];
            #pragma unroll
            for (int mi = 0; mi < 4; mi++) {
                int r = wm0 + mi * 16 + g;
                float v0 = as[r * 20 + kc + tg];
                float v1 = as[(r + 8) * 20 + kc + tg];
                float v2 = as[r * 20 + kc + tg + 4];
                float v3 = as[(r + 8) * 20 + kc + tg + 4];
                ah[mi][0] = t32h(v0); ah[mi][1] = t32h(v1);
                ah[mi][2] = t32h(v2); ah[mi][3] = t32h(v3);
                if (PRECISE) {
                    al[mi][0] = t32l(v0, ah[mi][0]); al[mi][1] = t32l(v1, ah[mi][1]);
                    al[mi][2] = t32l(v2, ah[mi][2]); al[mi][3] = t32l(v3, ah[mi][3]);
                }
            }
            #pragma unroll
            for (int nj = 0; nj < 4; nj++) {
                int c = wn0 + nj * 8 + g;
                float v0 = bs[(kc + tg) * 136 + c];
                float v1 = bs[(kc + tg + 4) * 136 + c];
                bh[nj][0] = t32h(v0); bh[nj][1] = t32h(v1);
                if (PRECISE) {
                    bl[nj][0] = t32l(v0, bh[nj][0]);
                    bl[nj][1] = t32l(v1, bh[nj][1]);
                }
            }
            #pragma unroll
            for (int mi = 0; mi < 4; mi++)
                #pragma unroll
                for (int nj = 0; nj < 4; nj++) {
                    MMA_TF32(acc[mi][nj], ah[mi][0], ah[mi][1], ah[mi][2], ah[mi][3],
                             bh[nj][0], bh[nj][1]);
                    if (PRECISE) {
                        MMA_TF32(acc[mi][nj], ah[mi][0], ah[mi][1], ah[mi][2], ah[mi][3],
                                 bl[nj][0], bl[nj][1]);
                        MMA_TF32(acc[mi][nj], al[mi][0], al[mi][1], al[mi][2], al[mi][3],
                                 bh[nj][0], bh[nj][1]);
                    }
                }
        }
        __syncthreads();
    }
    #undef LOAD_STAGE

    if (EPI == 0) {
        #pragma unroll
        for (int mi = 0; mi < 4; mi++) {
            int r = m0 + wm0 + mi * 16 + g;
            #pragma unroll
            for (int nj = 0; nj < 4; nj++) {
                int c = n0 + wn0 + nj * 8 + tg * 2;
                *(float2*)&C[(size_t)r * N + c] = make_float2(acc[mi][nj][0], acc[mi][nj][1]);
                *(float2*)&C[(size_t)(r + 8) * N + c] = make_float2(acc[mi][nj][2], acc[mi][nj][3]);
            }
        }
    } else {
        int region = n0 >> 10;   // 0=Q, 1=K, 2=V, 3=iq
        #pragma unroll
        for (int mi = 0; mi < 4; mi++) {
            int r = m0 + wm0 + mi * 16 + g;       // global token index (bt)
            int s = r & 2047;
            #pragma unroll
            for (int nj = 0; nj < 4; nj++) {
                int c = n0 + wn0 + nj * 8 + tg * 2;
                float a0 = acc[mi][nj][0], a1 = acc[mi][nj][1];
                float a2 = acc[mi][nj][2], a3 = acc[mi][nj][3];
                if (region == 3) {
                    int cc = c - 3072;
                    *(float2*)&C2[(size_t)r * 256 + cc] = make_float2(a0, a1);
                    *(float2*)&C2[(size_t)(r + 8) * 256 + cc] = make_float2(a2, a3);
                } else if (region == 2) {
                    int cc = c & 1023;
                    *(__half2*)(kvp + (size_t)r * 2048 + 1024 + cc) = __floats2half2_rn(a0, a1);
                    *(__half2*)(kvp + (size_t)(r + 8) * 2048 + 1024 + cc) = __floats2half2_rn(a2, a3);
                } else {
                    int cc = c & 1023;
                    int p = (cc & 63) >> 1;
                    float2 t0 = tab[s * 32 + p];
                    float2 t1 = tab[(s + 8) * 32 + p];
                    float y0 = a0 * t0.x - a1 * t0.y;
                    float y1 = a1 * t0.x + a0 * t0.y;
                    float y2 = a2 * t1.x - a3 * t1.y;
                    float y3 = a3 * t1.x + a2 * t1.y;
                    if (region == 0) {
                        *(float2*)&C[(size_t)r * 1024 + cc] = make_float2(y0, y1);
                        *(float2*)&C[(size_t)(r + 8) * 1024 + cc] = make_float2(y2, y3);
                    } else {
                        *(__half2*)(kvp + (size_t)r * 2048 + cc) = __floats2half2_rn(y0, y1);
                        *(__half2*)(kvp + (size_t)(r + 8) * 2048 + cc) = __floats2half2_rn(y2, y3);
                    }
                }
            }
        }
    }
}

// ---------------- scalar fp32 SGEMM (exact) for fused ik|iw ----------------
__global__ __launch_bounds__(256) void sgemm(const float* __restrict__ A,
                                             const float* __restrict__ B,
                                             float* __restrict__ C,
                                             int M, int N, int K) {
    __shared__ float As[64][17];
    __shared__ float Bs[16][64];
    int tid = threadIdx.x;
    int tx = tid & 15, ty = tid >> 4;
    int row0 = blockIdx.y * 64, col0 = blockIdx.x * 64;
    float acc[4][4] = {};
    for (int k0 = 0; k0 < K; k0 += 16) {
        #pragma unroll
        for (int i = 0; i < 4; i++) {
            int idx = tid + i * 256;
            int r = idx >> 4, kk = idx & 15;
            As[r][kk] = A[(size_t)(row0 + r) * K + k0 + kk];
        }
        #pragma unroll
        for (int i = 0; i < 4; i++) {
            int idx = tid + i * 256;
            int kk = idx >> 6, c = idx & 63;
            int col = col0 + c;
            Bs[kk][c] = (col < N) ? B[(size_t)(k0 + kk) * N + col] : 0.f;
        }
        __syncthreads();
        #pragma unroll
        for (int kk = 0; kk < 16; kk++) {
            float a[4], b[4];
            #pragma unroll
            for (int i = 0; i < 4; i++) a[i] = As[ty * 4 + i][kk];
            #pragma unroll
            for (int j = 0; j < 4; j++) b[j] = Bs[kk][tx * 4 + j];
            #pragma unroll
            for (int i = 0; i < 4; i++)
                #pragma unroll
                for (int j = 0; j < 4; j++)
                    acc[i][j] += a[i] * b[j];
        }
        __syncthreads();
    }
    #pragma unroll
    for (int i = 0; i < 4; i++) {
        int r = row0 + ty * 4 + i;
        #pragma unroll
        for (int j = 0; j < 4; j++) {
            int c = col0 + tx * 4 + j;
            if (c < N) C[(size_t)r * N + c] = acc[i][j];
        }
    }
}

// ---------------- pack Wk|Ww -> [1024, 68] ----------------------------------
__global__ __launch_bounds__(256) void pack_wkw(const float* __restrict__ Wk,
                                                const float* __restrict__ Ww,
                                                float* __restrict__ Wkw) {
    int idx = blockIdx.x * 256 + threadIdx.x;
    if (idx >= Dd * NKW) return;
    int row = idx / NKW, col = idx - row * NKW;
    Wkw[idx] = (col < 64) ? Wk[row * 64 + col] : Ww[row * IHh + (col - 64)];
}

__device__ __forceinline__ unsigned flipf(float f) {
    unsigned u = __float_as_uint(f);
    return (u & 0x80000000u) ? ~u : (u | 0x80000000u);
}

// ---------------- indexer scores + exact causal top-k ----------------------
__global__ __launch_bounds__(256) void indexer_topk(const float* __restrict__ iq,
                                                    const float* __restrict__ ikw,
                                                    int* __restrict__ sel,
                                                    int* __restrict__ cnt) {
    int bt = blockIdx.x;
    int b = bt >> 11, t = bt & 2047;
    int tid = threadIdx.x;
    int lane = tid & 31, w = tid >> 5;
    int n = t + 1;

    __shared__ float sq[IHh * IDd];
    __shared__ float sw[IHh];
    if (tid < IHh * IDd) sq[tid] = iq[(size_t)bt * IHh * IDd + tid];
    if (tid < IHh) sw[tid] = ikw[(size_t)bt * NKW + 64 + tid];

    if (n <= TOPK) {
        for (int s = tid; s < n; s += 256) sel[(size_t)bt * TOPK + s] = s;
        if (tid == 0) cnt[bt] = n;
        return;
    }
    __syncthreads();

    __shared__ float sc[Ss];
    for (int s = tid; s < n; s += 256) {
        const float4* k4 = (const float4*)(ikw + (size_t)(b * Ss + s) * NKW);
        float d0 = 0.f, d1 = 0.f, d2 = 0.f, d3 = 0.f;
        #pragma unroll
        for (int j4 = 0; j4 < 16; j4++) {
            float4 kv = k4[j4];
            int o = j4 * 4;
            d0 += sq[0*64+o]*kv.x + sq[0*64+o+1]*kv.y + sq[0*64+o+2]*kv.z + sq[0*64+o+3]*kv.w;
            d1 += sq[1*64+o]*kv.x + sq[1*64+o+1]*kv.y + sq[1*64+o+2]*kv.z + sq[1*64+o+3]*kv.w;
            d2 += sq[2*64+o]*kv.x + sq[2*64+o+1]*kv.y + sq[2*64+o+2]*kv.z + sq[2*64+o+3]*kv.w;
            d3 += sq[3*64+o]*kv.x + sq[3*64+o+1]*kv.y + sq[3*64+o+2]*kv.z + sq[3*64+o+3]*kv.w;
        }
        sc[s] = sw[0]*fmaxf(d0,0.f) + sw[1]*fmaxf(d1,0.f)
              + sw[2]*fmaxf(d2,0.f) + sw[3]*fmaxf(d3,0.f);
    }
    __syncthreads();

    __shared__ int hist[256];
    __shared__ int sfx[256];
    __shared__ unsigned sh_prefix;
    __shared__ int sh_krem;
    unsigned prefix = 0;
    int krem = TOPK;
    for (int pass = 0; pass < 4; pass++) {
        int shift = 24 - pass * 8;
        hist[tid] = 0;
        __syncthreads();
        for (int s0 = 0; s0 < n; s0 += 256) {
            int s = s0 + tid;
            bool valid = false;
            unsigned bin = 0;
            if (s < n) {
                unsigned key = flipf(sc[s]);
                if (((key >> shift) >> 8) == prefix) {
                    valid = true;
                    bin = (key >> shift) & 255;
                }
            }
            unsigned act = __ballot_sync(0xffffffffu, valid);
            if (valid) {
                unsigned peers = __match_any_sync(act, bin);
                if ((__ffs(peers) - 1) == lane)
                    atomicAdd(&hist[bin], __popc(peers));
            }
        }
        __syncthreads();
        int hv = hist[tid];
        sfx[tid] = hv;
        __syncthreads();
        #pragma unroll
        for (int off = 1; off < 256; off <<= 1) {
            int add = (tid + off < 256) ? sfx[tid + off] : 0;
            __syncthreads();
            sfx[tid] += add;
            __syncthreads();
        }
        int sf = sfx[tid];
        int sfn = (tid < 255) ? sfx[tid + 1] : 0;
        if (sf >= krem && sfn < krem) {
            sh_prefix = (prefix << 8) | (unsigned)tid;
            sh_krem = krem - sfn;
        }
        __syncthreads();
        prefix = sh_prefix;
        krem = sh_krem;
        __syncthreads();
    }
    unsigned T = prefix;

    __shared__ int nsel;
    if (tid == 0) nsel = 0;
    __syncthreads();
    for (int s = tid; s < n; s += 256) {
        if (flipf(sc[s]) > T) {
            int p = atomicAdd(&nsel, 1);
            sel[(size_t)bt * TOPK + p] = s;
        }
    }
    __syncthreads();

    __shared__ int warpcnt[8];
    __shared__ int eqbase;
    if (tid == 0) eqbase = 0;
    __syncthreads();
    for (int s0 = 0; s0 < n; s0 += 256) {
        int s = s0 + tid;
        bool eq = false;
        if (s < n) eq = (flipf(sc[s]) == T);
        unsigned bal = __ballot_sync(0xffffffffu, eq);
        if (lane == 0) warpcnt[w] = __popc(bal);
        __syncthreads();
        int wbase = 0;
        for (int i = 0; i < w; i++) wbase += warpcnt[i];
        int rank = eqbase + wbase + __popc(bal & ((1u << lane) - 1));
        if (eq && rank < krem) {
            int p = atomicAdd(&nsel, 1);
            sel[(size_t)bt * TOPK + p] = s;
        }
        __syncthreads();
        if (tid == 0) {
            int tot = 0;
            for (int i = 0; i < 8; i++) tot += warpcnt[i];
            eqbase += tot;
        }
        __syncthreads();
    }
    if (tid == 0) cnt[bt] = TOPK;
}

// ---------------- sparse SDPA: block per (b,t, head-half), warp per head ---
__global__ __launch_bounds__(256, 2) void sdpa(const float* __restrict__ qp,
                                               const __half* __restrict__ kv,
                                               const int* __restrict__ sel,
                                               const int* __restrict__ cnt,
                                               float* __restrict__ attn) {
    int bt = blockIdx.x;
    int b = bt >> 11;
    int tid = threadIdx.x;
    int w = tid >> 5, lane = tid & 31;
    int h = blockIdx.y * 8 + w;

    __shared__ float sQ[8 * DHh];
    __shared__ int   sSel[TOPK];
    __shared__ float sL[8][TOPK];

    int n = cnt[bt];
    const float* Qrow = qp + (size_t)bt * Dd + blockIdx.y * 512;
    for (int i = tid; i < 512; i += 256) sQ[i] = Qrow[i];
    for (int i = tid; i < n; i += 256) sSel[i] = sel[(size_t)bt * TOPK + i];
    __syncthreads();

    float qr[64];
    #pragma unroll
    for (int i = 0; i < 64; i += 4) {
        float4 tq = *(const float4*)&sQ[w * 64 + i];
        qr[i] = tq.x; qr[i+1] = tq.y; qr[i+2] = tq.z; qr[i+3] = tq.w;
    }

    const float scale = 0.125f;
    size_t kvbase = (size_t)b * Ss * 2048;

    // Phase A: logits (lane-per-key, fp16 K)
    for (int j0 = 0; j0 < n; j0 += 32) {
        int j = j0 + lane;
        if (j < n) {
            int s = sSel[j];
            const uint4* kp = (const uint4*)(kv + kvbase + (size_t)s * 2048 + h * 64);
            float d = 0.f;
            #pragma unroll
            for (int i = 0; i < 8; i++) {
                uint4 wv = kp[i];
                const __half2* p2 = (const __half2*)&wv;
                #pragma unroll
                for (int q = 0; q < 4; q++) {
                    float2 f = __half22float2(p2[q]);
                    d += qr[i*8 + q*2] * f.x + qr[i*8 + q*2 + 1] * f.y;
                }
            }
            sL[w][j] = d * scale;
        }
    }
    __syncwarp();

    // Phase B: softmax (warp-local per head)
    float m = -1e30f;
    for (int j = lane; j < n; j += 32) m = fmaxf(m, sL[w][j]);
    #pragma unroll
    for (int o = 16; o; o >>= 1) m = fmaxf(m, __shfl_xor_sync(0xffffffffu, m, o));
    float sum = 0.f;
    for (int j = lane; j < n; j += 32) {
        float p = __expf(sL[w][j] - m);
        sL[w][j] = p;
        sum += p;
    }
    #pragma unroll
    for (int o = 16; o; o >>= 1) sum += __shfl_xor_sync(0xffffffffu, sum, o);
    float inv = 1.f / sum;
    __syncwarp();

    // Phase C: P @ V, vectorized 4 keys/instruction.
    int kg = lane >> 3, dg = lane & 7;
    float acc[8] = {};
    #pragma unroll 4
    for (int j0 = 0; j0 < n; j0 += 4) {
        int j = j0 + kg;
        if (j < n) {
            float p = sL[w][j];
            int s = sSel[j];
            uint4 vv = *(const uint4*)(kv + kvbase + (size_t)s * 2048 + 1024 + h * 64 + dg * 8);
            const __half2* h2 = (const __half2*)&vv;
            #pragma unroll
            for (int q = 0; q < 4; q++) {
                float2 f = __half22float2(h2[q]);
                acc[2*q]     += p * f.x;
                acc[2*q + 1] += p * f.y;
            }
        }
    }
    #pragma unroll
    for (int q = 0; q < 8; q++) {
        acc[q] += __shfl_xor_sync(0xffffffffu, acc[q], 8);
        acc[q] += __shfl_xor_sync(0xffffffffu, acc[q], 16);
    }
    if (kg == 0) {
        size_t ob = (size_t)bt * Dd + h * 64 + dg * 8;
        float4 o0 = make_float4(acc[0] * inv, acc[1] * inv, acc[2] * inv, acc[3] * inv);
        float4 o1 = make_float4(acc[4] * inv, acc[5] * inv, acc[6] * inv, acc[7] * inv);
        *(float4*)&attn[ob]     = o0;
        *(float4*)&attn[ob + 4] = o1;
    }
}

// ---------------- launch ----------------------------------------------------
extern "C" void kernel_launch(void* const* d_in, const int* in_sizes, int n_in,
                              void* d_out, int out_size) {
    const float* x      = (const float*)d_in[0];
    const float* W_qkv  = (const float*)d_in[1];
    const float* W_o    = (const float*)d_in[2];
    const float* Wq_idx = (const float*)d_in[3];
    const float* Wk_idx = (const float*)d_in[4];
    const float* Ww_idx = (const float*)d_in[5];
    float* out = (float*)d_out;

    float *qp, *iq, *wkw, *ikw, *attn;
    float2* tab;
    __half* kv;
    int *sel, *cnt;
    cudaGetSymbolAddress((void**)&qp,   g_q);
    cudaGetSymbolAddress((void**)&kv,   g_kv);
    cudaGetSymbolAddress((void**)&tab,  g_tab);
    cudaGetSymbolAddress((void**)&iq,   g_iq);
    cudaGetSymbolAddress((void**)&wkw,  g_wkw);
    cudaGetSymbolAddress((void**)&ikw,  g_ikw);
    cudaGetSymbolAddress((void**)&attn, g_attn);
    cudaGetSymbolAddress((void**)&sel,  g_sel);
    cudaGetSymbolAddress((void**)&cnt,  g_cnt);

    const int M = BT;  // 4096

    // RoPE table
    rope_table<<<(Ss * 32 + 255) / 256, 256>>>(tab);
    // pack Wk|Ww (independent of the big GEMM; launch early)
    pack_wkw<<<(Dd * NKW + 255) / 256, 256>>>(Wk_idx, Ww_idx, wkw);
    // Fused QKV + iq projection, RoPE + fp16 K/V epilogue (bit-identical)
    gemm_tc<true, 1><<<dim3(NFUSE / 128, M / 128), 256>>>(
        x, W_qkv, qp, M, NFUSE, Dd, tab, kv, Wq_idx, iq);
    // ik|iw fused projection: exact fp32 (frozen selection numerics)
    sgemm<<<dim3(2, M / 64), 256>>>(x, wkw, ikw, M, NKW, Dd);
    // indexer scores + top-k selection
    indexer_topk<<<BT, 256>>>(iq, ikw, sel, cnt);
    // sparse attention (2 head-halves per (b,t))
    sdpa<<<dim3(BT, 2), 256>>>(qp, kv, sel, cnt, attn);
    // output projection (3xTF32)
    gemm_tc<true, 0><<<dim3(Dd / 128, M / 128), 256>>>(
        attn, W_o, out, M, Dd, Dd, nullptr, nullptr, nullptr, nullptr);
}